// round 13
// baseline (speedup 1.0000x reference)
#include <cuda_runtime.h>
#include <cstdint>
#include <math.h>

// Problem constants
#define BB 16
#define CC 32
#define TT 512
#define SS 128       // GAF_SIZE
#define NIMG (BB*CC) // 512
#define LATENT 128

// ---------------- scratch (no allocation allowed) ----------------
__device__ float g_gaf[(size_t)NIMG * 2 * SS * SS];      // NCHW (input to L1)
__device__ float g_h1 [(size_t)NIMG * 64 * 64 * 32];     // NHWC, tf32-rounded
__device__ float g_h2 [(size_t)NIMG * 32 * 32 * 64];     // NHWC, tf32-rounded
__device__ float g_h3 [(size_t)NIMG * 16 * 16 * 128];    // NHWC, tf32-rounded
__device__ float g_pp  [NIMG * 256];                     // per-image pooled sums (from L4)
__device__ float g_pbar[BB * 256];
__device__ float g_wr1[2 * 9 * 32];                      // L1: [ci][t][cout]
__device__ float g_wr2[(32 * 9)  * 64];                  // [k][cout], tf32 bits
__device__ float g_wr3[(64 * 9)  * 128];
__device__ float g_wr4[(128 * 9) * 256];

// ---------------- helpers ----------------
__device__ __forceinline__ uint32_t f2tf32(float f) {
    uint32_t o;
    asm("cvt.rna.tf32.f32 %0, %1;" : "=r"(o) : "f"(f));
    return o;
}
__device__ __forceinline__ float f2tf32f(float f) {
    return __uint_as_float(f2tf32(f));
}
__device__ __forceinline__ void mma_tf32(float* d, const uint32_t* a, const uint32_t* b) {
    asm volatile(
        "mma.sync.aligned.m16n8k8.row.col.f32.tf32.tf32.f32 "
        "{%0,%1,%2,%3}, {%4,%5,%6,%7}, {%8,%9}, {%0,%1,%2,%3};"
        : "+f"(d[0]), "+f"(d[1]), "+f"(d[2]), "+f"(d[3])
        : "r"(a[0]), "r"(a[1]), "r"(a[2]), "r"(a[3]), "r"(b[0]), "r"(b[1]));
}
__device__ __forceinline__ uint32_t smem_u32(const void* p) {
    uint32_t a;
    asm("{ .reg .u64 t; cvta.to.shared.u64 t, %1; cvt.u32.u64 %0, t; }" : "=r"(a) : "l"(p));
    return a;
}
__device__ __forceinline__ void cpasync16(uint32_t dst, const void* src, int srcsize) {
    asm volatile("cp.async.cg.shared.global [%0], [%1], 16, %2;"
                 :: "r"(dst), "l"(src), "r"(srcsize) : "memory");
}
#define CP_COMMIT() asm volatile("cp.async.commit_group;" ::: "memory")
#define CP_WAIT2()  asm volatile("cp.async.wait_group 2;" ::: "memory")
#define CP_WAIT1()  asm volatile("cp.async.wait_group 1;" ::: "memory")
#define CP_WAIT0()  asm volatile("cp.async.wait_group 0;" ::: "memory")

// ---------------- f32x2 helpers (L1 conv) ----------------
__device__ __forceinline__ unsigned long long pk2(float a, float b) {
    unsigned long long r;
    asm("mov.b64 %0, {%1, %2};" : "=l"(r) : "f"(a), "f"(b));
    return r;
}
__device__ __forceinline__ void upk2(unsigned long long v, float& a, float& b) {
    asm("mov.b64 {%0, %1}, %2;" : "=f"(a), "=f"(b) : "l"(v));
}
__device__ __forceinline__ void fma2(unsigned long long& d, unsigned long long a, unsigned long long b) {
    asm("fma.rn.f32x2 %0, %1, %2, %3;" : "=l"(d) : "l"(a), "l"(b), "l"(d));
}

// ---------------- merged weight repack ----------------
__device__ __forceinline__ void rp_tc(const float* __restrict__ W, uint32_t* __restrict__ Br,
                                      int CIN, int COUT, int idx)
{
    int co = idx % COUT;
    int k  = idx / COUT;
    int t  = k / CIN;
    int ci = k % CIN;
    Br[idx] = f2tf32(W[((size_t)co * CIN + ci) * 9 + t]);
}
__global__ void repack_all(const float* __restrict__ W1, const float* __restrict__ W2,
                           const float* __restrict__ W3, const float* __restrict__ W4)
{
    int idx = blockIdx.x * blockDim.x + threadIdx.x;
    if (idx < 576) {                       // L1: W[32][2][3][3] -> [ci][t][cout]
        int co = idx % 32;
        int t  = (idx / 32) % 9;
        int ci = idx / (32 * 9);
        g_wr1[idx] = W1[((size_t)co * 2 + ci) * 9 + t];
        return;
    }
    idx -= 576;
    if (idx < 288 * 64)  { rp_tc(W2, (uint32_t*)g_wr2, 32, 64, idx);  return; }
    idx -= 288 * 64;
    if (idx < 576 * 128) { rp_tc(W3, (uint32_t*)g_wr3, 64, 128, idx); return; }
    idx -= 576 * 128;
    if (idx < 1152 * 256) rp_tc(W4, (uint32_t*)g_wr4, 128, 256, idx);
}

// ---------------- GAF kernel (NCHW out), coalesced row stores ----------------
__global__ void gaf_kernel(const float* __restrict__ x_raw)
{
    const int img = blockIdx.x;
    const int tid = threadIdx.x;   // 0..127
    __shared__ float xs[SS];
    __shared__ float ssq[SS];
    __shared__ float smn[4], smx[4];

    const float4 v4 = *(const float4*)(x_raw + (size_t)img * TT + tid * 4);
    float v = 0.25f * (v4.x + v4.y + v4.z + v4.w);

    float mn = v, mx = v;
    #pragma unroll
    for (int o = 16; o > 0; o >>= 1) {
        mn = fminf(mn, __shfl_xor_sync(0xffffffffu, mn, o));
        mx = fmaxf(mx, __shfl_xor_sync(0xffffffffu, mx, o));
    }
    const int warp = tid >> 5, lane = tid & 31;
    if (lane == 0) { smn[warp] = mn; smx[warp] = mx; }
    __syncthreads();
    mn = fminf(fminf(smn[0], smn[1]), fminf(smn[2], smn[3]));
    mx = fmaxf(fmaxf(smx[0], smx[1]), fmaxf(smx[2], smx[3]));

    float xn = 2.0f * (v - mn) / (mx - mn + 1e-8f) - 1.0f;
    xn = fminf(1.0f, fmaxf(-1.0f, xn));
    float sq = sqrtf(fminf(1.0f, fmaxf(0.0f, 1.0f - xn * xn)));
    xs[tid] = xn;
    ssq[tid] = sq;
    __syncthreads();

    const int c0 = lane * 4;
    float xj[4], sj[4];
    #pragma unroll
    for (int c = 0; c < 4; c++) { xj[c] = xs[c0 + c]; sj[c] = ssq[c0 + c]; }
    float* __restrict__ g0 = g_gaf + (size_t)img * (2 * SS * SS);
    float* __restrict__ g1 = g0 + SS * SS;
    for (int rb = 0; rb < SS; rb += 4) {
        const int row = rb + warp;
        const float xi = xs[row], si = ssq[row];
        float4 o0, o1;
        o0.x = xi * xj[0] - si * sj[0];  o1.x = si * xj[0] - xi * sj[0];
        o0.y = xi * xj[1] - si * sj[1];  o1.y = si * xj[1] - xi * sj[1];
        o0.z = xi * xj[2] - si * sj[2];  o1.z = si * xj[2] - xi * sj[2];
        o0.w = xi * xj[3] - si * sj[3];  o1.w = si * xj[3] - xi * sj[3];
        *(float4*)(g0 + row * SS + c0) = o0;
        *(float4*)(g1 + row * SS + c0) = o1;
    }
}

// ---------------- L1 direct conv (FFMA2), NCHW in -> NHWC out (tf32-rounded) --------
__global__ void __launch_bounds__(128)
conv1_ffma2(const float* __restrict__ in, const float* __restrict__ Wr,
            const float* __restrict__ bias, float* __restrict__ out)
{
    constexpr int CIN = 2, HIN = 128, COUT = 32, HOUT = 64, WQ = 16;
    const int tid  = threadIdx.x;
    const int sid  = tid + blockIdx.z * 128;
    const int n    = blockIdx.x;
    const int cout0 = blockIdx.y * 8;
    const int oh  = sid / WQ;
    const int ow0 = (sid % WQ) * 4;

    const float* __restrict__ inN = in + (size_t)n * CIN * HIN * HIN;

    unsigned long long acc[4][4];
    #pragma unroll
    for (int cp = 0; cp < 4; cp++)
        #pragma unroll
        for (int o = 0; o < 4; o++) acc[cp][o] = 0ull;

    const bool rguard = (ow0 * 2 + 8 < HIN);

    #pragma unroll
    for (int ci = 0; ci < CIN; ci++) {
        const float* __restrict__ wbase = Wr + ((size_t)ci * 9) * COUT + cout0;
        const float* __restrict__ inC = inN + (size_t)ci * HIN * HIN;
        #pragma unroll
        for (int kh = 0; kh < 3; kh++) {
            const int ih = oh * 2 + kh;
            if (ih >= HIN) break;
            const float* row = inC + (size_t)ih * HIN + ow0 * 2;
            float r[9];
            const float4 a = *(const float4*)row;
            const float4 b = *(const float4*)(row + 4);
            r[0]=a.x; r[1]=a.y; r[2]=a.z; r[3]=a.w;
            r[4]=b.x; r[5]=b.y; r[6]=b.z; r[7]=b.w;
            r[8] = rguard ? row[8] : 0.0f;
            unsigned long long pb[9];
            #pragma unroll
            for (int v = 0; v < 9; v++) pb[v] = pk2(r[v], r[v]);
            #pragma unroll
            for (int kw = 0; kw < 3; kw++) {
                const float* wp = wbase + (kh * 3 + kw) * COUT;
                const ulonglong2 wa = *(const ulonglong2*)(wp);
                const ulonglong2 wb = *(const ulonglong2*)(wp + 4);
                #pragma unroll
                for (int o = 0; o < 4; o++) {
                    const unsigned long long x = pb[2 * o + kw];
                    fma2(acc[0][o], wa.x, x);
                    fma2(acc[1][o], wa.y, x);
                    fma2(acc[2][o], wb.x, x);
                    fma2(acc[3][o], wb.y, x);
                }
            }
        }
    }

    float bv[8];
    #pragma unroll
    for (int c = 0; c < 8; c++) bv[c] = __ldg(bias + cout0 + c);
    #pragma unroll
    for (int o = 0; o < 4; o++) {
        float l0,h0,l1,h1,l2,h2,l3,h3;
        upk2(acc[0][o], l0, h0); upk2(acc[1][o], l1, h1);
        upk2(acc[2][o], l2, h2); upk2(acc[3][o], l3, h3);
        float4 vlo, vhi;   // tf32-round outputs so downstream MMA truncation is exact
        vlo.x = f2tf32f(fmaxf(l0 + bv[0], 0.f)); vlo.y = f2tf32f(fmaxf(h0 + bv[1], 0.f));
        vlo.z = f2tf32f(fmaxf(l1 + bv[2], 0.f)); vlo.w = f2tf32f(fmaxf(h1 + bv[3], 0.f));
        vhi.x = f2tf32f(fmaxf(l2 + bv[4], 0.f)); vhi.y = f2tf32f(fmaxf(h2 + bv[5], 0.f));
        vhi.z = f2tf32f(fmaxf(l3 + bv[6], 0.f)); vhi.w = f2tf32f(fmaxf(h3 + bv[7], 0.f));
        float* op = out + (((size_t)n * HOUT + oh) * HOUT + (ow0 + o)) * COUT + cout0;
        *(float4*)op = vlo;
        *(float4*)(op + 4) = vhi;
    }
}

// ---------------- tf32 mma.sync implicit-GEMM conv ----------------
// 128-thread CTAs (4 warps), 4-slot cp.async ring, 1 chunk per barrier,
// graded wait_group (2/1/0), 2 CTAs/SM.
// OMODE: 1 = tf32-rounded NHWC store (feeds next MMA layer),
//        2 = fused global pooling: ReLU + sum over the CTA's TM(=P) rows -> g_pp
//            (requires TM == HOUT*HOUT, i.e., one image per CTA).
template<int CIN, int HIN, int COUTG, int NTILE, int TM, int WM, int WN, int OMODE>
__global__ void __launch_bounds__(128)
conv_mma(const float* __restrict__ in, const float* __restrict__ Br,
         const float* __restrict__ bias, float* __restrict__ out)
{
    static_assert(WM * WN == 4, "4 warps");
    constexpr int HOUT = HIN / 2;
    constexpr int P    = HOUT * HOUT;
    constexpr int K    = CIN * 9;
    constexpr int NCH  = K / 32;
    constexpr int CPT  = CIN / 32;
    constexpr int MF   = TM / (WM * 16);   // m fragments per warp
    constexpr int WNT  = NTILE / WN;       // warp n-tile
    constexpr int NF   = WNT / 8;          // n fragments per warp
    constexpr int AST  = 36;               // A smem row stride (floats)
    constexpr int BST  = NTILE + 8;        // B smem row stride (floats)
    constexpr int AFL  = TM * AST;
    constexpr int BFL  = 32 * BST;
    constexpr int SFL  = AFL + BFL;        // floats per stage
    constexpr int TPR  = 128 / TM;         // threads per A row
    constexpr int CHK  = 8 / TPR;          // 16B chunks per thread (A row = 128B)
    constexpr int BCH  = NTILE / 16;       // B cp.async iterations per thread

    extern __shared__ float smf[];
    const uint32_t sm0 = smem_u32(smf);

    const int tid  = threadIdx.x;
    const int lane = tid & 31;
    const int wid  = tid >> 5;
    const int wm   = wid % WM;
    const int wn   = wid / WM;
    const int g    = lane >> 2;           // 0..7
    const int tq   = lane & 3;            // 0..3

    // A staging coords
    const int r    = tid / TPR;
    const int sub  = tid % TPR;
    const int pos  = blockIdx.x * TM + r;
    const int nimg = pos / P;
    const int rem  = pos % P;
    const int oh   = rem / HOUT, ow = rem % HOUT;
    const int ncta = blockIdx.y * NTILE;

    const uint32_t a_dst_off = (uint32_t)(r * AST + sub * CHK * 4) * 4;

    auto prefetch = [&](int kc, int slot) {
        const uint32_t sbase = sm0 + (uint32_t)(slot * SFL) * 4;
        const int t   = kc / CPT;
        const int ci0 = (kc % CPT) * 32;
        const int kh = t / 3, kw = t % 3;
        const int ih = oh * 2 + kh, iw = ow * 2 + kw;
        const bool val = (ih < HIN) && (iw < HIN);
        const float* s = val
            ? in + ((((size_t)nimg * HIN + ih) * HIN + iw) * CIN + ci0) + sub * CHK * 4
            : in;
        const int sz = val ? 16 : 0;
        const uint32_t ad = sbase + a_dst_off;
        #pragma unroll
        for (int c = 0; c < CHK; c++)
            cpasync16(ad + c * 16, s + c * 4, sz);
        // B: 32 rows x NTILE floats (from COUTG-stride source)
        const uint32_t bd = sbase + (uint32_t)AFL * 4;
        #pragma unroll
        for (int j = 0; j < BCH; j++) {
            const int cid = j * 128 + tid;
            const int k   = cid / (NTILE / 4);
            const int cc  = cid % (NTILE / 4);
            cpasync16(bd + (uint32_t)(k * BST + cc * 4) * 4,
                      Br + (size_t)(kc * 32 + k) * COUTG + ncta + cc * 4, 16);
        }
    };

    prefetch(0, 0); CP_COMMIT();
    prefetch(1, 1); CP_COMMIT();
    prefetch(2, 2); CP_COMMIT();

    float d[MF][NF][4];
    #pragma unroll
    for (int mf = 0; mf < MF; mf++)
        #pragma unroll
        for (int nf = 0; nf < NF; nf++)
            #pragma unroll
            for (int j = 0; j < 4; j++) d[mf][nf][j] = 0.f;

    int slot = 0;
    for (int c = 0; c < NCH; c++) {
        if (c + 2 < NCH)      { CP_WAIT2(); }
        else if (c + 1 < NCH) { CP_WAIT1(); }
        else                  { CP_WAIT0(); }
        __syncthreads();     // chunk c visible; retires readers of slot (c+3)&3 (= (c-1)&3)
        if (c + 3 < NCH) {
            prefetch(c + 3, (c + 3) & 3);
            CP_COMMIT();
        }

        const uint32_t* A = (const uint32_t*)(smf + slot * SFL);
        const uint32_t* B = A + AFL;
        #pragma unroll
        for (int ks = 0; ks < 4; ks++) {
            uint32_t a[MF][4], b[NF][2];
            const int ac = ks * 8 + tq;
            #pragma unroll
            for (int mf = 0; mf < MF; mf++) {
                const int ar = wm * (16 * MF) + mf * 16 + g;
                a[mf][0] = A[ar * AST + ac];
                a[mf][1] = A[(ar + 8) * AST + ac];
                a[mf][2] = A[ar * AST + ac + 4];
                a[mf][3] = A[(ar + 8) * AST + ac + 4];
            }
            const int bkr = ks * 8 + tq;
            #pragma unroll
            for (int nf = 0; nf < NF; nf++) {
                const int bcc = wn * WNT + nf * 8 + g;
                b[nf][0] = B[bkr * BST + bcc];
                b[nf][1] = B[(bkr + 4) * BST + bcc];
            }
            #pragma unroll
            for (int mf = 0; mf < MF; mf++)
                #pragma unroll
                for (int nf = 0; nf < NF; nf++)
                    mma_tf32(d[mf][nf], a[mf], b[nf]);
        }
        slot = (slot + 1) & 3;
    }

    if (OMODE == 1) {
        // bias + ReLU + tf32 round, NHWC float2 stores
        #pragma unroll
        for (int nf = 0; nf < NF; nf++) {
            const int col = ncta + wn * WNT + nf * 8 + 2 * tq;
            const float b0 = __ldg(bias + col);
            const float b1 = __ldg(bias + col + 1);
            #pragma unroll
            for (int mf = 0; mf < MF; mf++) {
                const int row0 = blockIdx.x * TM + wm * (16 * MF) + mf * 16 + g;
                float2 v0, v1;
                v0.x = f2tf32f(fmaxf(d[mf][nf][0] + b0, 0.f));
                v0.y = f2tf32f(fmaxf(d[mf][nf][1] + b1, 0.f));
                v1.x = f2tf32f(fmaxf(d[mf][nf][2] + b0, 0.f));
                v1.y = f2tf32f(fmaxf(d[mf][nf][3] + b1, 0.f));
                *(float2*)(out + (size_t)row0 * COUTG + col)       = v0;
                *(float2*)(out + (size_t)(row0 + 8) * COUTG + col) = v1;
            }
        }
    } else {
        // OMODE == 2: fused pooling. TM == P: this CTA = one image, NTILE channels.
        // Per-thread: sum ReLU(d+bias) over its rows; reduce over g via shfl;
        // cross-warp via smem; write per-image channel sums to out (= g_pp).
        __syncthreads();   // all warps done reading smem slots before reuse
        float s[NF][2];
        #pragma unroll
        for (int nf = 0; nf < NF; nf++) {
            const int col = ncta + wn * WNT + nf * 8 + 2 * tq;
            const float b0 = __ldg(bias + col);
            const float b1 = __ldg(bias + col + 1);
            float s0 = 0.f, s1 = 0.f;
            #pragma unroll
            for (int mf = 0; mf < MF; mf++) {
                s0 += fmaxf(d[mf][nf][0] + b0, 0.f) + fmaxf(d[mf][nf][2] + b0, 0.f);
                s1 += fmaxf(d[mf][nf][1] + b1, 0.f) + fmaxf(d[mf][nf][3] + b1, 0.f);
            }
            // reduce over g (lane bits 2..4)
            #pragma unroll
            for (int o = 16; o >= 4; o >>= 1) {
                s0 += __shfl_xor_sync(0xffffffffu, s0, o);
                s1 += __shfl_xor_sync(0xffffffffu, s1, o);
            }
            s[nf][0] = s0; s[nf][1] = s1;
        }
        // smem: ps[wid][nf][tq][2]
        float* ps = smf;
        if (g == 0) {
            #pragma unroll
            for (int nf = 0; nf < NF; nf++) {
                ps[((wid * NF + nf) * 4 + tq) * 2 + 0] = s[nf][0];
                ps[((wid * NF + nf) * 4 + tq) * 2 + 1] = s[nf][1];
            }
        }
        __syncthreads();
        // one thread per output channel of this CTA's NTILE slice
        if (tid < NTILE) {
            const int wn_c = tid / WNT;
            const int rr   = tid % WNT;
            const int nf_c = rr >> 3;
            const int tq_c = (rr & 7) >> 1;
            const int j    = rr & 1;
            float sum = 0.f;
            #pragma unroll
            for (int wmc = 0; wmc < WM; wmc++) {
                const int w = wn_c * WM + wmc;
                sum += ps[((w * NF + nf_c) * 4 + tq_c) * 2 + j];
            }
            const int img = (blockIdx.x * TM) / P;
            out[(size_t)img * 256 + ncta + tid] = sum;
        }
    }
}

// ---------------- pool stage 2: sum over C=32 heads, divide ----------------
__global__ void pool2()
{
    const int b = blockIdx.x;
    const int k = threadIdx.x;
    const float* __restrict__ p = g_pp + (size_t)b * 32 * 256 + k;
    float s = 0.0f;
    #pragma unroll
    for (int c = 0; c < 32; c++)
        s += p[(size_t)c * 256];
    g_pbar[b * 256 + k] = s * (1.0f / 2048.0f);
}

// ---------------- FC ----------------
__global__ void fc_kernel(const float* __restrict__ Wfc, const float* __restrict__ bfc,
                          float* __restrict__ out)
{
    const int b = blockIdx.x;
    const int l = threadIdx.x;
    float s = bfc[l];
    const float* p = g_pbar + b * 256;
    #pragma unroll 8
    for (int k = 0; k < 256; k++)
        s = fmaf(p[k], Wfc[k * LATENT + l], s);
    out[b * LATENT + l] = s;
}

// ---------------- launch ----------------
extern "C" void kernel_launch(void* const* d_in, const int* in_sizes, int n_in,
                              void* d_out, int out_size)
{
    const float* x_raw = (const float*)d_in[0];
    const float* W1 = (const float*)d_in[1];  const float* b1 = (const float*)d_in[2];
    const float* W2 = (const float*)d_in[3];  const float* b2 = (const float*)d_in[4];
    const float* W3 = (const float*)d_in[5];  const float* b3 = (const float*)d_in[6];
    const float* W4 = (const float*)d_in[7];  const float* b4 = (const float*)d_in[8];
    const float* Wfc = (const float*)d_in[9]; const float* bfc = (const float*)d_in[10];
    float* out = (float*)d_out;

    float *gaf, *h1, *h2, *h3, *pp, *wr1, *wr2, *wr3, *wr4;
    cudaGetSymbolAddress((void**)&gaf, g_gaf);
    cudaGetSymbolAddress((void**)&h1, g_h1);
    cudaGetSymbolAddress((void**)&h2, g_h2);
    cudaGetSymbolAddress((void**)&h3, g_h3);
    cudaGetSymbolAddress((void**)&pp, g_pp);
    cudaGetSymbolAddress((void**)&wr1, g_wr1);
    cudaGetSymbolAddress((void**)&wr2, g_wr2);
    cudaGetSymbolAddress((void**)&wr3, g_wr3);
    cudaGetSymbolAddress((void**)&wr4, g_wr4);

    // 4-slot ring of (A + B) floats; 2 CTAs/SM
    const int smem2 = 4 * (128 * 36 + 32 * 72)  * 4;   // 110592
    const int smem3 = 4 * (64  * 36 + 32 * 136) * 4;   // 106496
    const int smem4 = 4 * (64  * 36 + 32 * 136) * 4;   // 106496
    cudaFuncSetAttribute((const void*)conv_mma<32, 64, 64, 64, 128, 2, 2, 1>,
                         cudaFuncAttributeMaxDynamicSharedMemorySize, smem2);
    cudaFuncSetAttribute((const void*)conv_mma<64, 32, 128, 128, 64, 2, 2, 1>,
                         cudaFuncAttributeMaxDynamicSharedMemorySize, smem3);
    cudaFuncSetAttribute((const void*)conv_mma<128, 16, 256, 128, 64, 2, 2, 2>,
                         cudaFuncAttributeMaxDynamicSharedMemorySize, smem4);

    const int rp_total = 576 + 288 * 64 + 576 * 128 + 1152 * 256;

    repack_all<<<(rp_total + 255) / 256, 256>>>(W1, W2, W3, W4);       // 0
    gaf_kernel<<<NIMG, 128>>>(x_raw);                                  // 1
    conv1_ffma2<<<dim3(NIMG, 4, 8), 128>>>(gaf, wr1, b1, h1);          // 2
    // L2: TM=128, warp tile 64x32 (MF=4, NF=4), 9 chunks
    conv_mma<32, 64, 64, 64, 128, 2, 2, 1>
        <<<dim3(NIMG * 1024 / 128, 1), 128, smem2>>>(h1, wr2, b2, h2); // 3
    // L3: TM=64, warp tile 32x64 (MF=2, NF=8), 18 chunks
    conv_mma<64, 32, 128, 128, 64, 2, 2, 1>
        <<<dim3(NIMG * 256 / 64, 1), 128, smem3>>>(h2, wr3, b3, h3);   // 4
    // L4: TM=64 (= one image), N split 2x128, fused pooling -> g_pp
    conv_mma<128, 16, 256, 128, 64, 2, 2, 2>
        <<<dim3(NIMG, 2), 128, smem4>>>(h3, wr4, b4, pp);              // 5
    pool2<<<BB, 256>>>();                                              // 6
    fc_kernel<<<BB, LATENT>>>(Wfc, bfc, out);                          // 7
}

// round 14
// speedup vs baseline: 1.5338x; 1.5338x over previous
#include <cuda_runtime.h>
#include <cstdint>
#include <math.h>

// Problem constants
#define BB 16
#define CC 32
#define TT 512
#define SS 128       // GAF_SIZE
#define NIMG (BB*CC) // 512
#define LATENT 128

// ---------------- scratch (no allocation allowed) ----------------
__device__ float g_gaf[(size_t)NIMG * 2 * SS * SS];      // NCHW (input to L1)
__device__ float g_h1 [(size_t)NIMG * 64 * 64 * 32];     // NHWC, tf32-rounded
__device__ float g_h2 [(size_t)NIMG * 32 * 32 * 64];     // NHWC, tf32-rounded
__device__ float g_h3 [(size_t)NIMG * 16 * 16 * 128];    // NHWC, tf32-rounded
__device__ float g_pp  [NIMG * 256];                     // per-image pooled sums (from L4)
__device__ float g_pbar[BB * 256];
__device__ float g_wr1[2 * 9 * 32];                      // L1: [ci][t][cout]
__device__ float g_wr2[(32 * 9)  * 64];                  // [k][cout], tf32 bits
__device__ float g_wr3[(64 * 9)  * 128];
__device__ float g_wr4[(128 * 9) * 256];

// ---------------- helpers ----------------
__device__ __forceinline__ uint32_t f2tf32(float f) {
    uint32_t o;
    asm("cvt.rna.tf32.f32 %0, %1;" : "=r"(o) : "f"(f));
    return o;
}
__device__ __forceinline__ float f2tf32f(float f) {
    return __uint_as_float(f2tf32(f));
}
__device__ __forceinline__ void mma_tf32(float* d, const uint32_t* a, const uint32_t* b) {
    asm volatile(
        "mma.sync.aligned.m16n8k8.row.col.f32.tf32.tf32.f32 "
        "{%0,%1,%2,%3}, {%4,%5,%6,%7}, {%8,%9}, {%0,%1,%2,%3};"
        : "+f"(d[0]), "+f"(d[1]), "+f"(d[2]), "+f"(d[3])
        : "r"(a[0]), "r"(a[1]), "r"(a[2]), "r"(a[3]), "r"(b[0]), "r"(b[1]));
}
__device__ __forceinline__ uint32_t smem_u32(const void* p) {
    uint32_t a;
    asm("{ .reg .u64 t; cvta.to.shared.u64 t, %1; cvt.u32.u64 %0, t; }" : "=r"(a) : "l"(p));
    return a;
}
__device__ __forceinline__ void cpasync16(uint32_t dst, const void* src, int srcsize) {
    asm volatile("cp.async.cg.shared.global [%0], [%1], 16, %2;"
                 :: "r"(dst), "l"(src), "r"(srcsize) : "memory");
}
#define CP_COMMIT() asm volatile("cp.async.commit_group;" ::: "memory")
#define CP_WAIT1()  asm volatile("cp.async.wait_group 1;" ::: "memory")
#define CP_WAIT0()  asm volatile("cp.async.wait_group 0;" ::: "memory")

// ---------------- f32x2 helpers (L1 conv) ----------------
__device__ __forceinline__ unsigned long long pk2(float a, float b) {
    unsigned long long r;
    asm("mov.b64 %0, {%1, %2};" : "=l"(r) : "f"(a), "f"(b));
    return r;
}
__device__ __forceinline__ void upk2(unsigned long long v, float& a, float& b) {
    asm("mov.b64 {%0, %1}, %2;" : "=f"(a), "=f"(b) : "l"(v));
}
__device__ __forceinline__ void fma2(unsigned long long& d, unsigned long long a, unsigned long long b) {
    asm("fma.rn.f32x2 %0, %1, %2, %3;" : "=l"(d) : "l"(a), "l"(b), "l"(d));
}

// ---------------- merged weight repack ----------------
__device__ __forceinline__ void rp_tc(const float* __restrict__ W, uint32_t* __restrict__ Br,
                                      int CIN, int COUT, int idx)
{
    int co = idx % COUT;
    int k  = idx / COUT;
    int t  = k / CIN;
    int ci = k % CIN;
    Br[idx] = f2tf32(W[((size_t)co * CIN + ci) * 9 + t]);
}
__global__ void repack_all(const float* __restrict__ W1, const float* __restrict__ W2,
                           const float* __restrict__ W3, const float* __restrict__ W4)
{
    int idx = blockIdx.x * blockDim.x + threadIdx.x;
    if (idx < 576) {                       // L1: W[32][2][3][3] -> [ci][t][cout]
        int co = idx % 32;
        int t  = (idx / 32) % 9;
        int ci = idx / (32 * 9);
        g_wr1[idx] = W1[((size_t)co * 2 + ci) * 9 + t];
        return;
    }
    idx -= 576;
    if (idx < 288 * 64)  { rp_tc(W2, (uint32_t*)g_wr2, 32, 64, idx);  return; }
    idx -= 288 * 64;
    if (idx < 576 * 128) { rp_tc(W3, (uint32_t*)g_wr3, 64, 128, idx); return; }
    idx -= 576 * 128;
    if (idx < 1152 * 256) rp_tc(W4, (uint32_t*)g_wr4, 128, 256, idx);
}

// ---------------- GAF kernel (NCHW out), coalesced row stores ----------------
__global__ void gaf_kernel(const float* __restrict__ x_raw)
{
    const int img = blockIdx.x;
    const int tid = threadIdx.x;   // 0..127
    __shared__ float xs[SS];
    __shared__ float ssq[SS];
    __shared__ float smn[4], smx[4];

    const float4 v4 = *(const float4*)(x_raw + (size_t)img * TT + tid * 4);
    float v = 0.25f * (v4.x + v4.y + v4.z + v4.w);

    float mn = v, mx = v;
    #pragma unroll
    for (int o = 16; o > 0; o >>= 1) {
        mn = fminf(mn, __shfl_xor_sync(0xffffffffu, mn, o));
        mx = fmaxf(mx, __shfl_xor_sync(0xffffffffu, mx, o));
    }
    const int warp = tid >> 5, lane = tid & 31;
    if (lane == 0) { smn[warp] = mn; smx[warp] = mx; }
    __syncthreads();
    mn = fminf(fminf(smn[0], smn[1]), fminf(smn[2], smn[3]));
    mx = fmaxf(fmaxf(smx[0], smx[1]), fmaxf(smx[2], smx[3]));

    float xn = 2.0f * (v - mn) / (mx - mn + 1e-8f) - 1.0f;
    xn = fminf(1.0f, fmaxf(-1.0f, xn));
    float sq = sqrtf(fminf(1.0f, fmaxf(0.0f, 1.0f - xn * xn)));
    xs[tid] = xn;
    ssq[tid] = sq;
    __syncthreads();

    const int c0 = lane * 4;
    float xj[4], sj[4];
    #pragma unroll
    for (int c = 0; c < 4; c++) { xj[c] = xs[c0 + c]; sj[c] = ssq[c0 + c]; }
    float* __restrict__ g0 = g_gaf + (size_t)img * (2 * SS * SS);
    float* __restrict__ g1 = g0 + SS * SS;
    for (int rb = 0; rb < SS; rb += 4) {
        const int row = rb + warp;
        const float xi = xs[row], si = ssq[row];
        float4 o0, o1;
        o0.x = xi * xj[0] - si * sj[0];  o1.x = si * xj[0] - xi * sj[0];
        o0.y = xi * xj[1] - si * sj[1];  o1.y = si * xj[1] - xi * sj[1];
        o0.z = xi * xj[2] - si * sj[2];  o1.z = si * xj[2] - xi * sj[2];
        o0.w = xi * xj[3] - si * sj[3];  o1.w = si * xj[3] - xi * sj[3];
        *(float4*)(g0 + row * SS + c0) = o0;
        *(float4*)(g1 + row * SS + c0) = o1;
    }
}

// ---------------- L1 direct conv (FFMA2), NCHW in -> NHWC out (tf32-rounded) --------
__global__ void __launch_bounds__(128)
conv1_ffma2(const float* __restrict__ in, const float* __restrict__ Wr,
            const float* __restrict__ bias, float* __restrict__ out)
{
    constexpr int CIN = 2, HIN = 128, COUT = 32, HOUT = 64, WQ = 16;
    const int tid  = threadIdx.x;
    const int sid  = tid + blockIdx.z * 128;
    const int n    = blockIdx.x;
    const int cout0 = blockIdx.y * 8;
    const int oh  = sid / WQ;
    const int ow0 = (sid % WQ) * 4;

    const float* __restrict__ inN = in + (size_t)n * CIN * HIN * HIN;

    unsigned long long acc[4][4];
    #pragma unroll
    for (int cp = 0; cp < 4; cp++)
        #pragma unroll
        for (int o = 0; o < 4; o++) acc[cp][o] = 0ull;

    const bool rguard = (ow0 * 2 + 8 < HIN);

    #pragma unroll
    for (int ci = 0; ci < CIN; ci++) {
        const float* __restrict__ wbase = Wr + ((size_t)ci * 9) * COUT + cout0;
        const float* __restrict__ inC = inN + (size_t)ci * HIN * HIN;
        #pragma unroll
        for (int kh = 0; kh < 3; kh++) {
            const int ih = oh * 2 + kh;
            if (ih >= HIN) break;
            const float* row = inC + (size_t)ih * HIN + ow0 * 2;
            float r[9];
            const float4 a = *(const float4*)row;
            const float4 b = *(const float4*)(row + 4);
            r[0]=a.x; r[1]=a.y; r[2]=a.z; r[3]=a.w;
            r[4]=b.x; r[5]=b.y; r[6]=b.z; r[7]=b.w;
            r[8] = rguard ? row[8] : 0.0f;
            unsigned long long pb[9];
            #pragma unroll
            for (int v = 0; v < 9; v++) pb[v] = pk2(r[v], r[v]);
            #pragma unroll
            for (int kw = 0; kw < 3; kw++) {
                const float* wp = wbase + (kh * 3 + kw) * COUT;
                const ulonglong2 wa = *(const ulonglong2*)(wp);
                const ulonglong2 wb = *(const ulonglong2*)(wp + 4);
                #pragma unroll
                for (int o = 0; o < 4; o++) {
                    const unsigned long long x = pb[2 * o + kw];
                    fma2(acc[0][o], wa.x, x);
                    fma2(acc[1][o], wa.y, x);
                    fma2(acc[2][o], wb.x, x);
                    fma2(acc[3][o], wb.y, x);
                }
            }
        }
    }

    float bv[8];
    #pragma unroll
    for (int c = 0; c < 8; c++) bv[c] = __ldg(bias + cout0 + c);
    #pragma unroll
    for (int o = 0; o < 4; o++) {
        float l0,h0,l1,h1,l2,h2,l3,h3;
        upk2(acc[0][o], l0, h0); upk2(acc[1][o], l1, h1);
        upk2(acc[2][o], l2, h2); upk2(acc[3][o], l3, h3);
        float4 vlo, vhi;   // tf32-round outputs so downstream MMA truncation is exact
        vlo.x = f2tf32f(fmaxf(l0 + bv[0], 0.f)); vlo.y = f2tf32f(fmaxf(h0 + bv[1], 0.f));
        vlo.z = f2tf32f(fmaxf(l1 + bv[2], 0.f)); vlo.w = f2tf32f(fmaxf(h1 + bv[3], 0.f));
        vhi.x = f2tf32f(fmaxf(l2 + bv[4], 0.f)); vhi.y = f2tf32f(fmaxf(h2 + bv[5], 0.f));
        vhi.z = f2tf32f(fmaxf(l3 + bv[6], 0.f)); vhi.w = f2tf32f(fmaxf(h3 + bv[7], 0.f));
        float* op = out + (((size_t)n * HOUT + oh) * HOUT + (ow0 + o)) * COUT + cout0;
        *(float4*)op = vlo;
        *(float4*)(op + 4) = vhi;
    }
}

// ---------------- tf32 mma.sync implicit-GEMM conv ----------------
// EXACT round-11 mainloop: 128-thread CTAs (4 warps), 3-stage cp.async ring,
// 1 chunk per barrier, CP_WAIT1 mid-loop, 2 CTAs/SM.
// OMODE: 1 = tf32-rounded NHWC store (feeds next MMA layer),
//        2 = fused global pooling: ReLU + sum over the CTA's TM(=P) rows -> g_pp
//            (requires TM == HOUT*HOUT, i.e., one image per CTA).
template<int CIN, int HIN, int COUTG, int NTILE, int TM, int WM, int WN, int OMODE>
__global__ void __launch_bounds__(128)
conv_mma(const float* __restrict__ in, const float* __restrict__ Br,
         const float* __restrict__ bias, float* __restrict__ out)
{
    static_assert(WM * WN == 4, "4 warps");
    constexpr int HOUT = HIN / 2;
    constexpr int P    = HOUT * HOUT;
    constexpr int K    = CIN * 9;
    constexpr int NCH  = K / 32;
    constexpr int CPT  = CIN / 32;
    constexpr int MF   = TM / (WM * 16);   // m fragments per warp
    constexpr int WNT  = NTILE / WN;       // warp n-tile
    constexpr int NF   = WNT / 8;          // n fragments per warp
    constexpr int AST  = 36;               // A smem row stride (floats)
    constexpr int BST  = NTILE + 8;        // B smem row stride (floats)
    constexpr int AFL  = TM * AST;
    constexpr int BFL  = 32 * BST;
    constexpr int SFL  = AFL + BFL;        // floats per stage
    constexpr int TPR  = 128 / TM;         // threads per A row
    constexpr int CHK  = 8 / TPR;          // 16B chunks per thread (A row = 128B)
    constexpr int BCH  = NTILE / 16;       // B cp.async iterations per thread

    extern __shared__ float smf[];
    const uint32_t sm0 = smem_u32(smf);

    const int tid  = threadIdx.x;
    const int lane = tid & 31;
    const int wid  = tid >> 5;
    const int wm   = wid % WM;
    const int wn   = wid / WM;
    const int g    = lane >> 2;           // 0..7
    const int tq   = lane & 3;            // 0..3

    // A staging coords
    const int r    = tid / TPR;
    const int sub  = tid % TPR;
    const int pos  = blockIdx.x * TM + r;
    const int nimg = pos / P;
    const int rem  = pos % P;
    const int oh   = rem / HOUT, ow = rem % HOUT;
    const int ncta = blockIdx.y * NTILE;

    const uint32_t a_dst_off = (uint32_t)(r * AST + sub * CHK * 4) * 4;

    auto prefetch = [&](int kc, int slot) {
        const uint32_t sbase = sm0 + (uint32_t)(slot * SFL) * 4;
        const int t   = kc / CPT;
        const int ci0 = (kc % CPT) * 32;
        const int kh = t / 3, kw = t % 3;
        const int ih = oh * 2 + kh, iw = ow * 2 + kw;
        const bool val = (ih < HIN) && (iw < HIN);
        const float* s = val
            ? in + ((((size_t)nimg * HIN + ih) * HIN + iw) * CIN + ci0) + sub * CHK * 4
            : in;
        const int sz = val ? 16 : 0;
        const uint32_t ad = sbase + a_dst_off;
        #pragma unroll
        for (int c = 0; c < CHK; c++)
            cpasync16(ad + c * 16, s + c * 4, sz);
        // B: 32 rows x NTILE floats (from COUTG-stride source)
        const uint32_t bd = sbase + (uint32_t)AFL * 4;
        #pragma unroll
        for (int j = 0; j < BCH; j++) {
            const int cid = j * 128 + tid;
            const int k   = cid / (NTILE / 4);
            const int cc  = cid % (NTILE / 4);
            cpasync16(bd + (uint32_t)(k * BST + cc * 4) * 4,
                      Br + (size_t)(kc * 32 + k) * COUTG + ncta + cc * 4, 16);
        }
    };

    prefetch(0, 0); CP_COMMIT();
    prefetch(1, 1); CP_COMMIT();

    float d[MF][NF][4];
    #pragma unroll
    for (int mf = 0; mf < MF; mf++)
        #pragma unroll
        for (int nf = 0; nf < NF; nf++)
            #pragma unroll
            for (int j = 0; j < 4; j++) d[mf][nf][j] = 0.f;

    int slot = 0;
    for (int c = 0; c < NCH; c++) {
        if (c + 1 < NCH) { CP_WAIT1(); } else { CP_WAIT0(); }
        __syncthreads();
        if (c + 2 < NCH) {
            int ps = slot + 2; if (ps >= 3) ps -= 3;
            prefetch(c + 2, ps);
            CP_COMMIT();
        }

        const uint32_t* A = (const uint32_t*)(smf + slot * SFL);
        const uint32_t* B = A + AFL;
        #pragma unroll
        for (int ks = 0; ks < 4; ks++) {
            uint32_t a[MF][4], b[NF][2];
            const int ac = ks * 8 + tq;
            #pragma unroll
            for (int mf = 0; mf < MF; mf++) {
                const int ar = wm * (16 * MF) + mf * 16 + g;
                a[mf][0] = A[ar * AST + ac];
                a[mf][1] = A[(ar + 8) * AST + ac];
                a[mf][2] = A[ar * AST + ac + 4];
                a[mf][3] = A[(ar + 8) * AST + ac + 4];
            }
            const int bkr = ks * 8 + tq;
            #pragma unroll
            for (int nf = 0; nf < NF; nf++) {
                const int bcc = wn * WNT + nf * 8 + g;
                b[nf][0] = B[bkr * BST + bcc];
                b[nf][1] = B[(bkr + 4) * BST + bcc];
            }
            #pragma unroll
            for (int mf = 0; mf < MF; mf++)
                #pragma unroll
                for (int nf = 0; nf < NF; nf++)
                    mma_tf32(d[mf][nf], a[mf], b[nf]);
        }
        if (++slot == 3) slot = 0;
    }

    if (OMODE == 1) {
        // bias + ReLU + tf32 round, NHWC float2 stores
        #pragma unroll
        for (int nf = 0; nf < NF; nf++) {
            const int col = ncta + wn * WNT + nf * 8 + 2 * tq;
            const float b0 = __ldg(bias + col);
            const float b1 = __ldg(bias + col + 1);
            #pragma unroll
            for (int mf = 0; mf < MF; mf++) {
                const int row0 = blockIdx.x * TM + wm * (16 * MF) + mf * 16 + g;
                float2 v0, v1;
                v0.x = f2tf32f(fmaxf(d[mf][nf][0] + b0, 0.f));
                v0.y = f2tf32f(fmaxf(d[mf][nf][1] + b1, 0.f));
                v1.x = f2tf32f(fmaxf(d[mf][nf][2] + b0, 0.f));
                v1.y = f2tf32f(fmaxf(d[mf][nf][3] + b1, 0.f));
                *(float2*)(out + (size_t)row0 * COUTG + col)       = v0;
                *(float2*)(out + (size_t)(row0 + 8) * COUTG + col) = v1;
            }
        }
    } else {
        // OMODE == 2: fused pooling. TM == P: this CTA = one image, NTILE channels.
        __syncthreads();   // all warps done with smem slots before reuse as scratch
        float s[NF][2];
        #pragma unroll
        for (int nf = 0; nf < NF; nf++) {
            const int col = ncta + wn * WNT + nf * 8 + 2 * tq;
            const float b0 = __ldg(bias + col);
            const float b1 = __ldg(bias + col + 1);
            float s0 = 0.f, s1 = 0.f;
            #pragma unroll
            for (int mf = 0; mf < MF; mf++) {
                s0 += fmaxf(d[mf][nf][0] + b0, 0.f) + fmaxf(d[mf][nf][2] + b0, 0.f);
                s1 += fmaxf(d[mf][nf][1] + b1, 0.f) + fmaxf(d[mf][nf][3] + b1, 0.f);
            }
            // reduce over g (lane bits 2..4)
            #pragma unroll
            for (int o = 16; o >= 4; o >>= 1) {
                s0 += __shfl_xor_sync(0xffffffffu, s0, o);
                s1 += __shfl_xor_sync(0xffffffffu, s1, o);
            }
            s[nf][0] = s0; s[nf][1] = s1;
        }
        // smem scratch: ps[wid][nf][tq][2]
        float* ps = smf;
        if (g == 0) {
            #pragma unroll
            for (int nf = 0; nf < NF; nf++) {
                ps[((wid * NF + nf) * 4 + tq) * 2 + 0] = s[nf][0];
                ps[((wid * NF + nf) * 4 + tq) * 2 + 1] = s[nf][1];
            }
        }
        __syncthreads();
        // one thread per output channel of this CTA's NTILE slice
        if (tid < NTILE) {
            const int wn_c = tid / WNT;
            const int rr   = tid % WNT;
            const int nf_c = rr >> 3;
            const int tq_c = (rr & 7) >> 1;
            const int j    = rr & 1;
            float sum = 0.f;
            #pragma unroll
            for (int wmc = 0; wmc < WM; wmc++) {
                const int w = wn_c * WM + wmc;
                sum += ps[((w * NF + nf_c) * 4 + tq_c) * 2 + j];
            }
            const int img = (blockIdx.x * TM) / P;
            out[(size_t)img * 256 + ncta + tid] = sum;
        }
    }
}

// ---------------- pool stage 2: sum over C=32 heads, divide ----------------
__global__ void pool2()
{
    const int b = blockIdx.x;
    const int k = threadIdx.x;
    const float* __restrict__ p = g_pp + (size_t)b * 32 * 256 + k;
    float s = 0.0f;
    #pragma unroll
    for (int c = 0; c < 32; c++)
        s += p[(size_t)c * 256];
    g_pbar[b * 256 + k] = s * (1.0f / 2048.0f);
}

// ---------------- FC ----------------
__global__ void fc_kernel(const float* __restrict__ Wfc, const float* __restrict__ bfc,
                          float* __restrict__ out)
{
    const int b = blockIdx.x;
    const int l = threadIdx.x;
    float s = bfc[l];
    const float* p = g_pbar + b * 256;
    #pragma unroll 8
    for (int k = 0; k < 256; k++)
        s = fmaf(p[k], Wfc[k * LATENT + l], s);
    out[b * LATENT + l] = s;
}

// ---------------- launch ----------------
extern "C" void kernel_launch(void* const* d_in, const int* in_sizes, int n_in,
                              void* d_out, int out_size)
{
    const float* x_raw = (const float*)d_in[0];
    const float* W1 = (const float*)d_in[1];  const float* b1 = (const float*)d_in[2];
    const float* W2 = (const float*)d_in[3];  const float* b2 = (const float*)d_in[4];
    const float* W3 = (const float*)d_in[5];  const float* b3 = (const float*)d_in[6];
    const float* W4 = (const float*)d_in[7];  const float* b4 = (const float*)d_in[8];
    const float* Wfc = (const float*)d_in[9]; const float* bfc = (const float*)d_in[10];
    float* out = (float*)d_out;

    float *gaf, *h1, *h2, *h3, *pp, *wr1, *wr2, *wr3, *wr4;
    cudaGetSymbolAddress((void**)&gaf, g_gaf);
    cudaGetSymbolAddress((void**)&h1, g_h1);
    cudaGetSymbolAddress((void**)&h2, g_h2);
    cudaGetSymbolAddress((void**)&h3, g_h3);
    cudaGetSymbolAddress((void**)&pp, g_pp);
    cudaGetSymbolAddress((void**)&wr1, g_wr1);
    cudaGetSymbolAddress((void**)&wr2, g_wr2);
    cudaGetSymbolAddress((void**)&wr3, g_wr3);
    cudaGetSymbolAddress((void**)&wr4, g_wr4);

    // 3 stages of (A + B) floats; ~80KB per CTA -> 2 CTAs/SM  (round-11 config)
    const int smem2 = 3 * (128 * 36 + 32 * 72)  * 4;   // 82944
    const int smem3 = 3 * (64  * 36 + 32 * 136) * 4;   // 79872
    const int smem4 = 3 * (64  * 36 + 32 * 136) * 4;   // 79872
    cudaFuncSetAttribute((const void*)conv_mma<32, 64, 64, 64, 128, 2, 2, 1>,
                         cudaFuncAttributeMaxDynamicSharedMemorySize, smem2);
    cudaFuncSetAttribute((const void*)conv_mma<64, 32, 128, 128, 64, 2, 2, 1>,
                         cudaFuncAttributeMaxDynamicSharedMemorySize, smem3);
    cudaFuncSetAttribute((const void*)conv_mma<128, 16, 256, 128, 64, 2, 2, 2>,
                         cudaFuncAttributeMaxDynamicSharedMemorySize, smem4);

    const int rp_total = 576 + 288 * 64 + 576 * 128 + 1152 * 256;

    repack_all<<<(rp_total + 255) / 256, 256>>>(W1, W2, W3, W4);       // 0
    gaf_kernel<<<NIMG, 128>>>(x_raw);                                  // 1
    conv1_ffma2<<<dim3(NIMG, 4, 8), 128>>>(gaf, wr1, b1, h1);          // 2
    // L2: TM=128, warp tile 64x32 (MF=4, NF=4), 9 chunks
    conv_mma<32, 64, 64, 64, 128, 2, 2, 1>
        <<<dim3(NIMG * 1024 / 128, 1), 128, smem2>>>(h1, wr2, b2, h2); // 3
    // L3: TM=64, warp tile 32x64 (MF=2, NF=8), 18 chunks
    conv_mma<64, 32, 128, 128, 64, 2, 2, 1>
        <<<dim3(NIMG * 256 / 64, 1), 128, smem3>>>(h2, wr3, b3, h3);   // 4
    // L4: TM=64 (= one image), N split 2x128, fused pooling -> g_pp
    conv_mma<128, 16, 256, 128, 64, 2, 2, 2>
        <<<dim3(NIMG, 2), 128, smem4>>>(h3, wr4, b4, pp);              // 5
    pool2<<<BB, 256>>>();                                              // 6
    fc_kernel<<<BB, LATENT>>>(Wfc, bfc, out);                          // 7
}

// round 15
// speedup vs baseline: 2.1174x; 1.3805x over previous
#include <cuda_runtime.h>
#include <cstdint>
#include <math.h>

// Problem constants
#define BB 16
#define CC 32
#define TT 512
#define SS 128       // GAF_SIZE
#define NIMG (BB*CC) // 512
#define LATENT 128

// ---------------- scratch (no allocation allowed) ----------------
__device__ float g_gaf[(size_t)NIMG * 2 * SS * SS];      // NCHW (input to L1)
__device__ float g_h1 [(size_t)NIMG * 64 * 64 * 32];     // NHWC, tf32-rounded
__device__ float g_h2 [(size_t)NIMG * 32 * 32 * 64];     // NHWC, tf32-rounded
__device__ float g_h3 [(size_t)NIMG * 16 * 16 * 128];    // NHWC, tf32-rounded
__device__ float g_pp  [NIMG * 256];                     // per-image pooled sums (from L4)
__device__ float g_pbar[BB * 256];
__device__ float g_wr1[2 * 9 * 32];                      // L1: [ci][t][cout]
__device__ float g_wr2[(32 * 9)  * 64];                  // [k][cout], tf32 bits
__device__ float g_wr3[(64 * 9)  * 128];
__device__ float g_wr4[(128 * 9) * 256];

// ---------------- helpers ----------------
__device__ __forceinline__ uint32_t f2tf32(float f) {
    uint32_t o;
    asm("cvt.rna.tf32.f32 %0, %1;" : "=r"(o) : "f"(f));
    return o;
}
__device__ __forceinline__ float f2tf32f(float f) {
    return __uint_as_float(f2tf32(f));
}
__device__ __forceinline__ void mma_tf32(float* d, const uint32_t* a, const uint32_t* b) {
    asm volatile(
        "mma.sync.aligned.m16n8k8.row.col.f32.tf32.tf32.f32 "
        "{%0,%1,%2,%3}, {%4,%5,%6,%7}, {%8,%9}, {%0,%1,%2,%3};"
        : "+f"(d[0]), "+f"(d[1]), "+f"(d[2]), "+f"(d[3])
        : "r"(a[0]), "r"(a[1]), "r"(a[2]), "r"(a[3]), "r"(b[0]), "r"(b[1]));
}
__device__ __forceinline__ uint32_t smem_u32(const void* p) {
    uint32_t a;
    asm("{ .reg .u64 t; cvta.to.shared.u64 t, %1; cvt.u32.u64 %0, t; }" : "=r"(a) : "l"(p));
    return a;
}
__device__ __forceinline__ void cpasync16(uint32_t dst, const void* src, int srcsize) {
    asm volatile("cp.async.cg.shared.global [%0], [%1], 16, %2;"
                 :: "r"(dst), "l"(src), "r"(srcsize) : "memory");
}
#define CP_COMMIT() asm volatile("cp.async.commit_group;" ::: "memory")
#define CP_WAIT1()  asm volatile("cp.async.wait_group 1;" ::: "memory")
#define CP_WAIT0()  asm volatile("cp.async.wait_group 0;" ::: "memory")

// ---------------- f32x2 helpers (L1 conv) ----------------
__device__ __forceinline__ unsigned long long pk2(float a, float b) {
    unsigned long long r;
    asm("mov.b64 %0, {%1, %2};" : "=l"(r) : "f"(a), "f"(b));
    return r;
}
__device__ __forceinline__ void upk2(unsigned long long v, float& a, float& b) {
    asm("mov.b64 {%0, %1}, %2;" : "=f"(a), "=f"(b) : "l"(v));
}
__device__ __forceinline__ void fma2(unsigned long long& d, unsigned long long a, unsigned long long b) {
    asm("fma.rn.f32x2 %0, %1, %2, %3;" : "=l"(d) : "l"(a), "l"(b), "l"(d));
}

// ---------------- merged weight repack ----------------
__device__ __forceinline__ void rp_tc(const float* __restrict__ W, uint32_t* __restrict__ Br,
                                      int CIN, int COUT, int idx)
{
    int co = idx % COUT;
    int k  = idx / COUT;
    int t  = k / CIN;
    int ci = k % CIN;
    Br[idx] = f2tf32(W[((size_t)co * CIN + ci) * 9 + t]);
}
__global__ void repack_all(const float* __restrict__ W1, const float* __restrict__ W2,
                           const float* __restrict__ W3, const float* __restrict__ W4)
{
    int idx = blockIdx.x * blockDim.x + threadIdx.x;
    if (idx < 576) {                       // L1: W[32][2][3][3] -> [ci][t][cout]
        int co = idx % 32;
        int t  = (idx / 32) % 9;
        int ci = idx / (32 * 9);
        g_wr1[idx] = W1[((size_t)co * 2 + ci) * 9 + t];
        return;
    }
    idx -= 576;
    if (idx < 288 * 64)  { rp_tc(W2, (uint32_t*)g_wr2, 32, 64, idx);  return; }
    idx -= 288 * 64;
    if (idx < 576 * 128) { rp_tc(W3, (uint32_t*)g_wr3, 64, 128, idx); return; }
    idx -= 576 * 128;
    if (idx < 1152 * 256) rp_tc(W4, (uint32_t*)g_wr4, 128, 256, idx);
}

// ---------------- GAF kernel (NCHW out), coalesced row stores ----------------
__global__ void gaf_kernel(const float* __restrict__ x_raw)
{
    const int img = blockIdx.x;
    const int tid = threadIdx.x;   // 0..127
    __shared__ float xs[SS];
    __shared__ float ssq[SS];
    __shared__ float smn[4], smx[4];

    const float4 v4 = *(const float4*)(x_raw + (size_t)img * TT + tid * 4);
    float v = 0.25f * (v4.x + v4.y + v4.z + v4.w);

    float mn = v, mx = v;
    #pragma unroll
    for (int o = 16; o > 0; o >>= 1) {
        mn = fminf(mn, __shfl_xor_sync(0xffffffffu, mn, o));
        mx = fmaxf(mx, __shfl_xor_sync(0xffffffffu, mx, o));
    }
    const int warp = tid >> 5, lane = tid & 31;
    if (lane == 0) { smn[warp] = mn; smx[warp] = mx; }
    __syncthreads();
    mn = fminf(fminf(smn[0], smn[1]), fminf(smn[2], smn[3]));
    mx = fmaxf(fmaxf(smx[0], smx[1]), fmaxf(smx[2], smx[3]));

    float xn = 2.0f * (v - mn) / (mx - mn + 1e-8f) - 1.0f;
    xn = fminf(1.0f, fmaxf(-1.0f, xn));
    float sq = sqrtf(fminf(1.0f, fmaxf(0.0f, 1.0f - xn * xn)));
    xs[tid] = xn;
    ssq[tid] = sq;
    __syncthreads();

    const int c0 = lane * 4;
    float xj[4], sj[4];
    #pragma unroll
    for (int c = 0; c < 4; c++) { xj[c] = xs[c0 + c]; sj[c] = ssq[c0 + c]; }
    float* __restrict__ g0 = g_gaf + (size_t)img * (2 * SS * SS);
    float* __restrict__ g1 = g0 + SS * SS;
    for (int rb = 0; rb < SS; rb += 4) {
        const int row = rb + warp;
        const float xi = xs[row], si = ssq[row];
        float4 o0, o1;
        o0.x = xi * xj[0] - si * sj[0];  o1.x = si * xj[0] - xi * sj[0];
        o0.y = xi * xj[1] - si * sj[1];  o1.y = si * xj[1] - xi * sj[1];
        o0.z = xi * xj[2] - si * sj[2];  o1.z = si * xj[2] - xi * sj[2];
        o0.w = xi * xj[3] - si * sj[3];  o1.w = si * xj[3] - xi * sj[3];
        *(float4*)(g0 + row * SS + c0) = o0;
        *(float4*)(g1 + row * SS + c0) = o1;
    }
}

// ---------------- L1 direct conv (FFMA2), NCHW in -> NHWC out (tf32-rounded) --------
__global__ void __launch_bounds__(128)
conv1_ffma2(const float* __restrict__ in, const float* __restrict__ Wr,
            const float* __restrict__ bias, float* __restrict__ out)
{
    constexpr int CIN = 2, HIN = 128, COUT = 32, HOUT = 64, WQ = 16;
    const int tid  = threadIdx.x;
    const int sid  = tid + blockIdx.z * 128;
    const int n    = blockIdx.x;
    const int cout0 = blockIdx.y * 8;
    const int oh  = sid / WQ;
    const int ow0 = (sid % WQ) * 4;

    const float* __restrict__ inN = in + (size_t)n * CIN * HIN * HIN;

    unsigned long long acc[4][4];
    #pragma unroll
    for (int cp = 0; cp < 4; cp++)
        #pragma unroll
        for (int o = 0; o < 4; o++) acc[cp][o] = 0ull;

    const bool rguard = (ow0 * 2 + 8 < HIN);

    #pragma unroll
    for (int ci = 0; ci < CIN; ci++) {
        const float* __restrict__ wbase = Wr + ((size_t)ci * 9) * COUT + cout0;
        const float* __restrict__ inC = inN + (size_t)ci * HIN * HIN;
        #pragma unroll
        for (int kh = 0; kh < 3; kh++) {
            const int ih = oh * 2 + kh;
            if (ih >= HIN) break;
            const float* row = inC + (size_t)ih * HIN + ow0 * 2;
            float r[9];
            const float4 a = *(const float4*)row;
            const float4 b = *(const float4*)(row + 4);
            r[0]=a.x; r[1]=a.y; r[2]=a.z; r[3]=a.w;
            r[4]=b.x; r[5]=b.y; r[6]=b.z; r[7]=b.w;
            r[8] = rguard ? row[8] : 0.0f;
            unsigned long long pb[9];
            #pragma unroll
            for (int v = 0; v < 9; v++) pb[v] = pk2(r[v], r[v]);
            #pragma unroll
            for (int kw = 0; kw < 3; kw++) {
                const float* wp = wbase + (kh * 3 + kw) * COUT;
                const ulonglong2 wa = *(const ulonglong2*)(wp);
                const ulonglong2 wb = *(const ulonglong2*)(wp + 4);
                #pragma unroll
                for (int o = 0; o < 4; o++) {
                    const unsigned long long x = pb[2 * o + kw];
                    fma2(acc[0][o], wa.x, x);
                    fma2(acc[1][o], wa.y, x);
                    fma2(acc[2][o], wb.x, x);
                    fma2(acc[3][o], wb.y, x);
                }
            }
        }
    }

    float bv[8];
    #pragma unroll
    for (int c = 0; c < 8; c++) bv[c] = __ldg(bias + cout0 + c);
    #pragma unroll
    for (int o = 0; o < 4; o++) {
        float l0,h0,l1,h1,l2,h2,l3,h3;
        upk2(acc[0][o], l0, h0); upk2(acc[1][o], l1, h1);
        upk2(acc[2][o], l2, h2); upk2(acc[3][o], l3, h3);
        float4 vlo, vhi;   // tf32-round outputs so downstream MMA truncation is exact
        vlo.x = f2tf32f(fmaxf(l0 + bv[0], 0.f)); vlo.y = f2tf32f(fmaxf(h0 + bv[1], 0.f));
        vlo.z = f2tf32f(fmaxf(l1 + bv[2], 0.f)); vlo.w = f2tf32f(fmaxf(h1 + bv[3], 0.f));
        vhi.x = f2tf32f(fmaxf(l2 + bv[4], 0.f)); vhi.y = f2tf32f(fmaxf(h2 + bv[5], 0.f));
        vhi.z = f2tf32f(fmaxf(l3 + bv[6], 0.f)); vhi.w = f2tf32f(fmaxf(h3 + bv[7], 0.f));
        float* op = out + (((size_t)n * HOUT + oh) * HOUT + (ow0 + o)) * COUT + cout0;
        *(float4*)op = vlo;
        *(float4*)(op + 4) = vhi;
    }
}

// ---------------- tf32 mma.sync implicit-GEMM conv ----------------
// Round-11 mainloop (3-stage ring, 1 chunk/barrier, CP_WAIT1, 4 warps, 2 CTAs/SM)
// with XOR-swizzled PACKED A tile (128B rows, chunk' = c16 ^ (row&7)):
//   - staging: lanes 0..7 cover one row contiguously -> 4 lines/warp-instr (was 32)
//   - fragment LDS conflict-free without padding (banks (2ks^g)*4+tq all distinct)
// OMODE: 1 = tf32-rounded NHWC store; 2 = fused global pooling -> g_pp (TM == P).
template<int CIN, int HIN, int COUTG, int NTILE, int TM, int WM, int WN, int OMODE>
__global__ void __launch_bounds__(128)
conv_mma(const float* __restrict__ in, const float* __restrict__ Br,
         const float* __restrict__ bias, float* __restrict__ out)
{
    static_assert(WM * WN == 4, "4 warps");
    constexpr int HOUT = HIN / 2;
    constexpr int P    = HOUT * HOUT;
    constexpr int K    = CIN * 9;
    constexpr int NCH  = K / 32;
    constexpr int CPT  = CIN / 32;
    constexpr int MF   = TM / (WM * 16);   // m fragments per warp
    constexpr int WNT  = NTILE / WN;       // warp n-tile
    constexpr int NF   = WNT / 8;          // n fragments per warp
    constexpr int BST  = NTILE + 8;        // B smem row stride (floats)
    constexpr int AFL  = TM * 32;          // packed A: 32 floats (128B) per row
    constexpr int BFL  = 32 * BST;
    constexpr int SFL  = AFL + BFL;        // floats per stage
    constexpr int AIT  = TM / 16;          // A cp.async iterations per thread
    constexpr int BCH  = NTILE / 16;       // B cp.async iterations per thread

    extern __shared__ float smf[];
    const uint32_t sm0 = smem_u32(smf);

    const int tid  = threadIdx.x;
    const int lane = tid & 31;
    const int wid  = tid >> 5;
    const int wm   = wid % WM;
    const int wn   = wid / WM;
    const int g    = lane >> 2;           // 0..7
    const int tq   = lane & 3;            // 0..3

    const int ncta = blockIdx.y * NTILE;

    // A staging precompute: thread handles chunk c16 = tid&7 of rows row0 + 16*it
    const int c16  = tid & 7;
    const int row0 = tid >> 3;
    const uint32_t a_swz_off = (uint32_t)((c16 ^ (row0 & 7)) * 16);  // row&7 == row0&7
    int  abase[AIT];         // tap-(0,0) global float offset for each of my rows
    uint32_t bflags = 0;     // per-it: bit0 = oh at max, bit1 = ow at max
    #pragma unroll
    for (int it = 0; it < AIT; it++) {
        const int row = row0 + 16 * it;
        const int pos = blockIdx.x * TM + row;
        const int n   = pos / P;
        const int rem = pos % P;
        const int oh  = rem / HOUT, ow = rem % HOUT;
        abase[it] = ((n * HIN + 2 * oh) * HIN + 2 * ow) * CIN + c16 * 4;
        if (oh == HOUT - 1) bflags |= 1u << (2 * it);
        if (ow == HOUT - 1) bflags |= 2u << (2 * it);
    }

    auto prefetch = [&](int kc, int slot) {
        const uint32_t sbase = sm0 + (uint32_t)(slot * SFL) * 4;
        const int t   = kc / CPT;
        const int ci0 = (kc % CPT) * 32;
        const int kh = t / 3, kw = t % 3;
        const int tap = (kh * HIN + kw) * CIN + ci0;
        const uint32_t ad = sbase + a_swz_off;
        #pragma unroll
        for (int it = 0; it < AIT; it++) {
            const bool val = !(((bflags >> (2 * it)) & 1u) && kh == 2) &&
                             !(((bflags >> (2 * it)) & 2u) && kw == 2);
            const float* s = val ? (in + abase[it] + tap) : in;
            cpasync16(ad + (uint32_t)(row0 + 16 * it) * 128, s, val ? 16 : 0);
        }
        // B: 32 rows x NTILE floats (from COUTG-stride source)
        const uint32_t bd = sbase + (uint32_t)AFL * 4;
        #pragma unroll
        for (int j = 0; j < BCH; j++) {
            const int cid = j * 128 + tid;
            const int k   = cid / (NTILE / 4);
            const int cc  = cid % (NTILE / 4);
            cpasync16(bd + (uint32_t)(k * BST + cc * 4) * 4,
                      Br + (size_t)(kc * 32 + k) * COUTG + ncta + cc * 4, 16);
        }
    };

    prefetch(0, 0); CP_COMMIT();
    prefetch(1, 1); CP_COMMIT();

    float d[MF][NF][4];
    #pragma unroll
    for (int mf = 0; mf < MF; mf++)
        #pragma unroll
        for (int nf = 0; nf < NF; nf++)
            #pragma unroll
            for (int j = 0; j < 4; j++) d[mf][nf][j] = 0.f;

    int slot = 0;
    for (int c = 0; c < NCH; c++) {
        if (c + 1 < NCH) { CP_WAIT1(); } else { CP_WAIT0(); }
        __syncthreads();
        if (c + 2 < NCH) {
            int ps = slot + 2; if (ps >= 3) ps -= 3;
            prefetch(c + 2, ps);
            CP_COMMIT();
        }

        const uint32_t* A = (const uint32_t*)(smf + slot * SFL);
        const uint32_t* B = A + AFL;
        #pragma unroll
        for (int ks = 0; ks < 4; ks++) {
            uint32_t a[MF][4], b[NF][2];
            const int s0 = ((2 * ks) ^ g) * 4 + tq;   // swizzled col of logical ks*8+tq
            const int s1 = s0 ^ 4;                    // swizzled col of logical ks*8+tq+4
            #pragma unroll
            for (int mf = 0; mf < MF; mf++) {
                const int ar = wm * (16 * MF) + mf * 16 + g;   // ar&7 == g
                a[mf][0] = A[ar * 32 + s0];
                a[mf][1] = A[(ar + 8) * 32 + s0];
                a[mf][2] = A[ar * 32 + s1];
                a[mf][3] = A[(ar + 8) * 32 + s1];
            }
            const int bkr = ks * 8 + tq;
            #pragma unroll
            for (int nf = 0; nf < NF; nf++) {
                const int bcc = wn * WNT + nf * 8 + g;
                b[nf][0] = B[bkr * BST + bcc];
                b[nf][1] = B[(bkr + 4) * BST + bcc];
            }
            #pragma unroll
            for (int mf = 0; mf < MF; mf++)
                #pragma unroll
                for (int nf = 0; nf < NF; nf++)
                    mma_tf32(d[mf][nf], a[mf], b[nf]);
        }
        if (++slot == 3) slot = 0;
    }

    if (OMODE == 1) {
        // bias + ReLU + tf32 round, NHWC float2 stores
        #pragma unroll
        for (int nf = 0; nf < NF; nf++) {
            const int col = ncta + wn * WNT + nf * 8 + 2 * tq;
            const float b0 = __ldg(bias + col);
            const float b1 = __ldg(bias + col + 1);
            #pragma unroll
            for (int mf = 0; mf < MF; mf++) {
                const int row0s = blockIdx.x * TM + wm * (16 * MF) + mf * 16 + g;
                float2 v0, v1;
                v0.x = f2tf32f(fmaxf(d[mf][nf][0] + b0, 0.f));
                v0.y = f2tf32f(fmaxf(d[mf][nf][1] + b1, 0.f));
                v1.x = f2tf32f(fmaxf(d[mf][nf][2] + b0, 0.f));
                v1.y = f2tf32f(fmaxf(d[mf][nf][3] + b1, 0.f));
                *(float2*)(out + (size_t)row0s * COUTG + col)       = v0;
                *(float2*)(out + (size_t)(row0s + 8) * COUTG + col) = v1;
            }
        }
    } else {
        // OMODE == 2: fused pooling. TM == P: this CTA = one image, NTILE channels.
        __syncthreads();   // all warps done with smem slots before reuse as scratch
        float s[NF][2];
        #pragma unroll
        for (int nf = 0; nf < NF; nf++) {
            const int col = ncta + wn * WNT + nf * 8 + 2 * tq;
            const float b0 = __ldg(bias + col);
            const float b1 = __ldg(bias + col + 1);
            float s0 = 0.f, s1 = 0.f;
            #pragma unroll
            for (int mf = 0; mf < MF; mf++) {
                s0 += fmaxf(d[mf][nf][0] + b0, 0.f) + fmaxf(d[mf][nf][2] + b0, 0.f);
                s1 += fmaxf(d[mf][nf][1] + b1, 0.f) + fmaxf(d[mf][nf][3] + b1, 0.f);
            }
            // reduce over g (lane bits 2..4)
            #pragma unroll
            for (int o = 16; o >= 4; o >>= 1) {
                s0 += __shfl_xor_sync(0xffffffffu, s0, o);
                s1 += __shfl_xor_sync(0xffffffffu, s1, o);
            }
            s[nf][0] = s0; s[nf][1] = s1;
        }
        // smem scratch: ps[wid][nf][tq][2]
        float* ps = smf;
        if (g == 0) {
            #pragma unroll
            for (int nf = 0; nf < NF; nf++) {
                ps[((wid * NF + nf) * 4 + tq) * 2 + 0] = s[nf][0];
                ps[((wid * NF + nf) * 4 + tq) * 2 + 1] = s[nf][1];
            }
        }
        __syncthreads();
        // one thread per output channel of this CTA's NTILE slice
        if (tid < NTILE) {
            const int wn_c = tid / WNT;
            const int rr   = tid % WNT;
            const int nf_c = rr >> 3;
            const int tq_c = (rr & 7) >> 1;
            const int j    = rr & 1;
            float sum = 0.f;
            #pragma unroll
            for (int wmc = 0; wmc < WM; wmc++) {
                const int w = wn_c * WM + wmc;
                sum += ps[((w * NF + nf_c) * 4 + tq_c) * 2 + j];
            }
            const int img = (blockIdx.x * TM) / P;
            out[(size_t)img * 256 + ncta + tid] = sum;
        }
    }
}

// ---------------- pool stage 2: sum over C=32 heads, divide ----------------
__global__ void pool2()
{
    const int b = blockIdx.x;
    const int k = threadIdx.x;
    const float* __restrict__ p = g_pp + (size_t)b * 32 * 256 + k;
    float s = 0.0f;
    #pragma unroll
    for (int c = 0; c < 32; c++)
        s += p[(size_t)c * 256];
    g_pbar[b * 256 + k] = s * (1.0f / 2048.0f);
}

// ---------------- FC ----------------
__global__ void fc_kernel(const float* __restrict__ Wfc, const float* __restrict__ bfc,
                          float* __restrict__ out)
{
    const int b = blockIdx.x;
    const int l = threadIdx.x;
    float s = bfc[l];
    const float* p = g_pbar + b * 256;
    #pragma unroll 8
    for (int k = 0; k < 256; k++)
        s = fmaf(p[k], Wfc[k * LATENT + l], s);
    out[b * LATENT + l] = s;
}

// ---------------- launch ----------------
extern "C" void kernel_launch(void* const* d_in, const int* in_sizes, int n_in,
                              void* d_out, int out_size)
{
    const float* x_raw = (const float*)d_in[0];
    const float* W1 = (const float*)d_in[1];  const float* b1 = (const float*)d_in[2];
    const float* W2 = (const float*)d_in[3];  const float* b2 = (const float*)d_in[4];
    const float* W3 = (const float*)d_in[5];  const float* b3 = (const float*)d_in[6];
    const float* W4 = (const float*)d_in[7];  const float* b4 = (const float*)d_in[8];
    const float* Wfc = (const float*)d_in[9]; const float* bfc = (const float*)d_in[10];
    float* out = (float*)d_out;

    float *gaf, *h1, *h2, *h3, *pp, *wr1, *wr2, *wr3, *wr4;
    cudaGetSymbolAddress((void**)&gaf, g_gaf);
    cudaGetSymbolAddress((void**)&h1, g_h1);
    cudaGetSymbolAddress((void**)&h2, g_h2);
    cudaGetSymbolAddress((void**)&h3, g_h3);
    cudaGetSymbolAddress((void**)&pp, g_pp);
    cudaGetSymbolAddress((void**)&wr1, g_wr1);
    cudaGetSymbolAddress((void**)&wr2, g_wr2);
    cudaGetSymbolAddress((void**)&wr3, g_wr3);
    cudaGetSymbolAddress((void**)&wr4, g_wr4);

    // 3 stages of (packed A + B) floats; 76.8KB per CTA -> 2 CTAs/SM
    const int smem2 = 3 * (128 * 32 + 32 * 72)  * 4;   // 76800
    const int smem3 = 3 * (64  * 32 + 32 * 136) * 4;   // 76800
    const int smem4 = 3 * (64  * 32 + 32 * 136) * 4;   // 76800
    cudaFuncSetAttribute((const void*)conv_mma<32, 64, 64, 64, 128, 2, 2, 1>,
                         cudaFuncAttributeMaxDynamicSharedMemorySize, smem2);
    cudaFuncSetAttribute((const void*)conv_mma<64, 32, 128, 128, 64, 2, 2, 1>,
                         cudaFuncAttributeMaxDynamicSharedMemorySize, smem3);
    cudaFuncSetAttribute((const void*)conv_mma<128, 16, 256, 128, 64, 2, 2, 2>,
                         cudaFuncAttributeMaxDynamicSharedMemorySize, smem4);

    const int rp_total = 576 + 288 * 64 + 576 * 128 + 1152 * 256;

    repack_all<<<(rp_total + 255) / 256, 256>>>(W1, W2, W3, W4);       // 0
    gaf_kernel<<<NIMG, 128>>>(x_raw);                                  // 1
    conv1_ffma2<<<dim3(NIMG, 4, 8), 128>>>(gaf, wr1, b1, h1);          // 2
    // L2: TM=128, warp tile 64x32 (MF=4, NF=4), 9 chunks
    conv_mma<32, 64, 64, 64, 128, 2, 2, 1>
        <<<dim3(NIMG * 1024 / 128, 1), 128, smem2>>>(h1, wr2, b2, h2); // 3
    // L3: TM=64, warp tile 32x64 (MF=2, NF=8), 18 chunks
    conv_mma<64, 32, 128, 128, 64, 2, 2, 1>
        <<<dim3(NIMG * 256 / 64, 1), 128, smem3>>>(h2, wr3, b3, h3);   // 4
    // L4: TM=64 (= one image), N split 2x128, fused pooling -> g_pp
    conv_mma<128, 16, 256, 128, 64, 2, 2, 2>
        <<<dim3(NIMG, 2), 128, smem4>>>(h3, wr4, b4, pp);              // 5
    pool2<<<BB, 256>>>();                                              // 6
    fc_kernel<<<BB, LATENT>>>(Wfc, bfc, out);                          // 7
}

// round 16
// speedup vs baseline: 2.4037x; 1.1352x over previous
#include <cuda_runtime.h>
#include <cstdint>
#include <math.h>

// Problem constants
#define BB 16
#define CC 32
#define TT 512
#define SS 128       // GAF_SIZE
#define NIMG (BB*CC) // 512
#define LATENT 128

// ---------------- scratch (no allocation allowed) ----------------
__device__ float g_gaf[(size_t)NIMG * SS * SS * 2];      // NHWC (C=2), tf32-rounded
__device__ float g_h1 [(size_t)NIMG * 64 * 64 * 32];     // NHWC, tf32-rounded
__device__ float g_h2 [(size_t)NIMG * 32 * 32 * 64];     // NHWC, tf32-rounded
__device__ float g_h3 [(size_t)NIMG * 16 * 16 * 128];    // NHWC, tf32-rounded
__device__ float g_pp  [NIMG * 256];                     // per-image pooled sums (from L4)
__device__ float g_pbar[BB * 256];
__device__ float g_wr1[32 * 32];                         // L1 MMA: [k][cout], k=kh*8+kw*2+ci, tf32
__device__ float g_wr2[(32 * 9)  * 64];                  // [k][cout], tf32 bits
__device__ float g_wr3[(64 * 9)  * 128];
__device__ float g_wr4[(128 * 9) * 256];

// ---------------- helpers ----------------
__device__ __forceinline__ uint32_t f2tf32(float f) {
    uint32_t o;
    asm("cvt.rna.tf32.f32 %0, %1;" : "=r"(o) : "f"(f));
    return o;
}
__device__ __forceinline__ float f2tf32f(float f) {
    return __uint_as_float(f2tf32(f));
}
__device__ __forceinline__ void mma_tf32(float* d, const uint32_t* a, const uint32_t* b) {
    asm volatile(
        "mma.sync.aligned.m16n8k8.row.col.f32.tf32.tf32.f32 "
        "{%0,%1,%2,%3}, {%4,%5,%6,%7}, {%8,%9}, {%0,%1,%2,%3};"
        : "+f"(d[0]), "+f"(d[1]), "+f"(d[2]), "+f"(d[3])
        : "r"(a[0]), "r"(a[1]), "r"(a[2]), "r"(a[3]), "r"(b[0]), "r"(b[1]));
}
__device__ __forceinline__ uint32_t smem_u32(const void* p) {
    uint32_t a;
    asm("{ .reg .u64 t; cvta.to.shared.u64 t, %1; cvt.u32.u64 %0, t; }" : "=r"(a) : "l"(p));
    return a;
}
__device__ __forceinline__ void cpasync16(uint32_t dst, const void* src, int srcsize) {
    asm volatile("cp.async.cg.shared.global [%0], [%1], 16, %2;"
                 :: "r"(dst), "l"(src), "r"(srcsize) : "memory");
}
__device__ __forceinline__ void cpasync8(uint32_t dst, const void* src, int srcsize) {
    asm volatile("cp.async.ca.shared.global [%0], [%1], 8, %2;"
                 :: "r"(dst), "l"(src), "r"(srcsize) : "memory");
}
#define CP_COMMIT() asm volatile("cp.async.commit_group;" ::: "memory")
#define CP_WAIT1()  asm volatile("cp.async.wait_group 1;" ::: "memory")
#define CP_WAIT0()  asm volatile("cp.async.wait_group 0;" ::: "memory")

// ---------------- merged weight repack ----------------
__device__ __forceinline__ void rp_tc(const float* __restrict__ W, uint32_t* __restrict__ Br,
                                      int CIN, int COUT, int idx)
{
    int co = idx % COUT;
    int k  = idx / COUT;
    int t  = k / CIN;
    int ci = k % CIN;
    Br[idx] = f2tf32(W[((size_t)co * CIN + ci) * 9 + t]);
}
__global__ void repack_all(const float* __restrict__ W1, const float* __restrict__ W2,
                           const float* __restrict__ W3, const float* __restrict__ W4)
{
    int idx = blockIdx.x * blockDim.x + threadIdx.x;
    if (idx < 1024) {                      // L1 MMA: [k][cout], k = kh*8 + kw*2 + ci
        int co = idx % 32;
        int k  = idx / 32;
        int kh = k >> 3, r = k & 7;
        float v = 0.0f;
        if (kh < 3 && r < 6) {
            int kw = r >> 1, ci = r & 1;
            v = W1[((size_t)(co * 2 + ci)) * 9 + kh * 3 + kw];
        }
        ((uint32_t*)g_wr1)[idx] = f2tf32(v);
        return;
    }
    idx -= 1024;
    if (idx < 288 * 64)  { rp_tc(W2, (uint32_t*)g_wr2, 32, 64, idx);  return; }
    idx -= 288 * 64;
    if (idx < 576 * 128) { rp_tc(W3, (uint32_t*)g_wr3, 64, 128, idx); return; }
    idx -= 576 * 128;
    if (idx < 1152 * 256) rp_tc(W4, (uint32_t*)g_wr4, 128, 256, idx);
}

// ---------------- GAF kernel: NHWC (C=2) tf32-rounded output ----------------
__global__ void gaf_kernel(const float* __restrict__ x_raw)
{
    const int img = blockIdx.x;
    const int tid = threadIdx.x;   // 0..127
    __shared__ float xs[SS];
    __shared__ float ssq[SS];
    __shared__ float smn[4], smx[4];

    const float4 v4 = *(const float4*)(x_raw + (size_t)img * TT + tid * 4);
    float v = 0.25f * (v4.x + v4.y + v4.z + v4.w);

    float mn = v, mx = v;
    #pragma unroll
    for (int o = 16; o > 0; o >>= 1) {
        mn = fminf(mn, __shfl_xor_sync(0xffffffffu, mn, o));
        mx = fmaxf(mx, __shfl_xor_sync(0xffffffffu, mx, o));
    }
    const int warp = tid >> 5, lane = tid & 31;
    if (lane == 0) { smn[warp] = mn; smx[warp] = mx; }
    __syncthreads();
    mn = fminf(fminf(smn[0], smn[1]), fminf(smn[2], smn[3]));
    mx = fmaxf(fmaxf(smx[0], smx[1]), fmaxf(smx[2], smx[3]));

    float xn = 2.0f * (v - mn) / (mx - mn + 1e-8f) - 1.0f;
    xn = fminf(1.0f, fmaxf(-1.0f, xn));
    float sq = sqrtf(fminf(1.0f, fmaxf(0.0f, 1.0f - xn * xn)));
    xs[tid] = xn;
    ssq[tid] = sq;
    __syncthreads();

    const int c0 = lane * 4;
    float xj[4], sj[4];
    #pragma unroll
    for (int c = 0; c < 4; c++) { xj[c] = xs[c0 + c]; sj[c] = ssq[c0 + c]; }
    float* __restrict__ gb = g_gaf + (size_t)img * (SS * SS * 2);
    for (int rb = 0; rb < SS; rb += 4) {
        const int row = rb + warp;
        const float xi = xs[row], si = ssq[row];
        float4 q0, q1;   // interleaved (gasf, gadf) pairs, tf32-rounded
        q0.x = f2tf32f(xi * xj[0] - si * sj[0]);  q0.y = f2tf32f(si * xj[0] - xi * sj[0]);
        q0.z = f2tf32f(xi * xj[1] - si * sj[1]);  q0.w = f2tf32f(si * xj[1] - xi * sj[1]);
        q1.x = f2tf32f(xi * xj[2] - si * sj[2]);  q1.y = f2tf32f(si * xj[2] - xi * sj[2]);
        q1.z = f2tf32f(xi * xj[3] - si * sj[3]);  q1.w = f2tf32f(si * xj[3] - xi * sj[3]);
        float* gp = gb + ((size_t)row * SS + c0) * 2;
        *(float4*)gp       = q0;
        *(float4*)(gp + 4) = q1;
    }
}

// ---------------- L1 conv via tf32 MMA (single chunk, K=24 eff) ----------------
// in: g_gaf NHWC C=2 tf32; Br: g_wr1 [k][32]; out: h1 NHWC 32ch tf32-rounded.
// M tile 128, N=32, warps 2x2 (warp tile 64x16: MF=4, NF=2), 3 ks-steps.
__global__ void __launch_bounds__(128)
conv1_mma(const float* __restrict__ in, const float* __restrict__ Br,
          const float* __restrict__ bias, float* __restrict__ out)
{
    constexpr int AST = 36;                 // A row stride (floats), bank-clean
    constexpr int BST = 40;
    constexpr int AFL = 128 * AST;
    constexpr int HIN = 128, HOUT = 64, P = 4096;

    extern __shared__ float smf[];
    const uint32_t sm0 = smem_u32(smf);

    const int tid  = threadIdx.x;
    const int lane = tid & 31;
    const int wid  = tid >> 5;
    const int wm   = wid & 1;
    const int wn   = wid >> 1;
    const int g    = lane >> 2;
    const int tq   = lane & 3;

    // A staging: thread = row
    const int pos = blockIdx.x * 128 + tid;
    const int n   = pos >> 12;
    const int rem = pos & (P - 1);
    const int oh  = rem >> 6, ow = rem & 63;
    const float* base = in + (((size_t)n * HIN + 2 * oh) * HIN + 2 * ow) * 2;
    const uint32_t ad = sm0 + (uint32_t)tid * AST * 4;

    // zero the pad columns of my A row (k = 6,7,14,15,22,23; ks3 block unused)
    {
        float* Arow = smf + tid * AST;
        *(float2*)(Arow + 6)  = make_float2(0.f, 0.f);
        *(float2*)(Arow + 14) = make_float2(0.f, 0.f);
        *(float2*)(Arow + 22) = make_float2(0.f, 0.f);
    }

    #pragma unroll
    for (int kh = 0; kh < 3; kh++) {
        const bool v16 = !(oh == 63 && kh == 2);
        const bool v8  = v16 && (ow != 63);
        const float* s = base + kh * (HIN * 2);
        cpasync16(ad + kh * 32,      s,     v16 ? 16 : 0);
        cpasync8 (ad + kh * 32 + 16, s + 4, v8  ? 8  : 0);
    }
    // B: 32 rows x 32 floats
    {
        const uint32_t bd = sm0 + (uint32_t)AFL * 4;
        #pragma unroll
        for (int j = 0; j < 2; j++) {
            const int cid = j * 128 + tid;
            const int k   = cid >> 3;
            const int cc  = cid & 7;
            cpasync16(bd + (uint32_t)(k * BST + cc * 4) * 4, Br + k * 32 + cc * 4, 16);
        }
    }
    CP_COMMIT();

    float d[4][2][4];
    #pragma unroll
    for (int mf = 0; mf < 4; mf++)
        #pragma unroll
        for (int nf = 0; nf < 2; nf++)
            #pragma unroll
            for (int j = 0; j < 4; j++) d[mf][nf][j] = 0.f;

    CP_WAIT0();
    __syncthreads();

    const uint32_t* A = (const uint32_t*)smf;
    const uint32_t* B = A + AFL;
    #pragma unroll
    for (int ks = 0; ks < 3; ks++) {        // k 24..31 are all-zero weights: skipped
        uint32_t a[4][4], b[2][2];
        const int ac = ks * 8 + tq;
        #pragma unroll
        for (int mf = 0; mf < 4; mf++) {
            const int ar = wm * 64 + mf * 16 + g;
            a[mf][0] = A[ar * AST + ac];
            a[mf][1] = A[(ar + 8) * AST + ac];
            a[mf][2] = A[ar * AST + ac + 4];
            a[mf][3] = A[(ar + 8) * AST + ac + 4];
        }
        const int bkr = ks * 8 + tq;
        #pragma unroll
        for (int nf = 0; nf < 2; nf++) {
            const int bcc = wn * 16 + nf * 8 + g;
            b[nf][0] = B[bkr * BST + bcc];
            b[nf][1] = B[(bkr + 4) * BST + bcc];
        }
        #pragma unroll
        for (int mf = 0; mf < 4; mf++)
            #pragma unroll
            for (int nf = 0; nf < 2; nf++)
                mma_tf32(d[mf][nf], a[mf], b[nf]);
    }

    // epilogue: bias + ReLU + tf32 round, NHWC (32ch) float2 stores
    #pragma unroll
    for (int nf = 0; nf < 2; nf++) {
        const int col = wn * 16 + nf * 8 + 2 * tq;
        const float b0 = __ldg(bias + col);
        const float b1 = __ldg(bias + col + 1);
        #pragma unroll
        for (int mf = 0; mf < 4; mf++) {
            const int row0s = blockIdx.x * 128 + wm * 64 + mf * 16 + g;
            float2 v0, v1;
            v0.x = f2tf32f(fmaxf(d[mf][nf][0] + b0, 0.f));
            v0.y = f2tf32f(fmaxf(d[mf][nf][1] + b1, 0.f));
            v1.x = f2tf32f(fmaxf(d[mf][nf][2] + b0, 0.f));
            v1.y = f2tf32f(fmaxf(d[mf][nf][3] + b1, 0.f));
            *(float2*)(out + (size_t)row0s * 32 + col)       = v0;
            *(float2*)(out + (size_t)(row0s + 8) * 32 + col) = v1;
        }
    }
}

// ---------------- tf32 mma.sync implicit-GEMM conv (layers 2-4) ----------------
// Round-15 winner: 3-stage ring, 1 chunk/barrier, CP_WAIT1, 4 warps, 2 CTAs/SM,
// XOR-swizzled PACKED A tile (128B rows, chunk' = c16 ^ (row&7)).
// OMODE: 1 = tf32-rounded NHWC store; 2 = fused global pooling -> g_pp (TM == P).
template<int CIN, int HIN, int COUTG, int NTILE, int TM, int WM, int WN, int OMODE>
__global__ void __launch_bounds__(128)
conv_mma(const float* __restrict__ in, const float* __restrict__ Br,
         const float* __restrict__ bias, float* __restrict__ out)
{
    static_assert(WM * WN == 4, "4 warps");
    constexpr int HOUT = HIN / 2;
    constexpr int P    = HOUT * HOUT;
    constexpr int K    = CIN * 9;
    constexpr int NCH  = K / 32;
    constexpr int CPT  = CIN / 32;
    constexpr int MF   = TM / (WM * 16);   // m fragments per warp
    constexpr int WNT  = NTILE / WN;       // warp n-tile
    constexpr int NF   = WNT / 8;          // n fragments per warp
    constexpr int BST  = NTILE + 8;        // B smem row stride (floats)
    constexpr int AFL  = TM * 32;          // packed A: 32 floats (128B) per row
    constexpr int BFL  = 32 * BST;
    constexpr int SFL  = AFL + BFL;        // floats per stage
    constexpr int AIT  = TM / 16;          // A cp.async iterations per thread
    constexpr int BCH  = NTILE / 16;       // B cp.async iterations per thread

    extern __shared__ float smf[];
    const uint32_t sm0 = smem_u32(smf);

    const int tid  = threadIdx.x;
    const int lane = tid & 31;
    const int wid  = tid >> 5;
    const int wm   = wid % WM;
    const int wn   = wid / WM;
    const int g    = lane >> 2;           // 0..7
    const int tq   = lane & 3;            // 0..3

    const int ncta = blockIdx.y * NTILE;

    // A staging precompute: thread handles chunk c16 = tid&7 of rows row0 + 16*it
    const int c16  = tid & 7;
    const int row0 = tid >> 3;
    const uint32_t a_swz_off = (uint32_t)((c16 ^ (row0 & 7)) * 16);  // row&7 == row0&7
    int  abase[AIT];
    uint32_t bflags = 0;
    #pragma unroll
    for (int it = 0; it < AIT; it++) {
        const int row = row0 + 16 * it;
        const int pos = blockIdx.x * TM + row;
        const int n   = pos / P;
        const int rem = pos % P;
        const int oh  = rem / HOUT, ow = rem % HOUT;
        abase[it] = ((n * HIN + 2 * oh) * HIN + 2 * ow) * CIN + c16 * 4;
        if (oh == HOUT - 1) bflags |= 1u << (2 * it);
        if (ow == HOUT - 1) bflags |= 2u << (2 * it);
    }

    auto prefetch = [&](int kc, int slot) {
        const uint32_t sbase = sm0 + (uint32_t)(slot * SFL) * 4;
        const int t   = kc / CPT;
        const int ci0 = (kc % CPT) * 32;
        const int kh = t / 3, kw = t % 3;
        const int tap = (kh * HIN + kw) * CIN + ci0;
        const uint32_t ad = sbase + a_swz_off;
        #pragma unroll
        for (int it = 0; it < AIT; it++) {
            const bool val = !(((bflags >> (2 * it)) & 1u) && kh == 2) &&
                             !(((bflags >> (2 * it)) & 2u) && kw == 2);
            const float* s = val ? (in + abase[it] + tap) : in;
            cpasync16(ad + (uint32_t)(row0 + 16 * it) * 128, s, val ? 16 : 0);
        }
        const uint32_t bd = sbase + (uint32_t)AFL * 4;
        #pragma unroll
        for (int j = 0; j < BCH; j++) {
            const int cid = j * 128 + tid;
            const int k   = cid / (NTILE / 4);
            const int cc  = cid % (NTILE / 4);
            cpasync16(bd + (uint32_t)(k * BST + cc * 4) * 4,
                      Br + (size_t)(kc * 32 + k) * COUTG + ncta + cc * 4, 16);
        }
    };

    prefetch(0, 0); CP_COMMIT();
    prefetch(1, 1); CP_COMMIT();

    float d[MF][NF][4];
    #pragma unroll
    for (int mf = 0; mf < MF; mf++)
        #pragma unroll
        for (int nf = 0; nf < NF; nf++)
            #pragma unroll
            for (int j = 0; j < 4; j++) d[mf][nf][j] = 0.f;

    int slot = 0;
    for (int c = 0; c < NCH; c++) {
        if (c + 1 < NCH) { CP_WAIT1(); } else { CP_WAIT0(); }
        __syncthreads();
        if (c + 2 < NCH) {
            int ps = slot + 2; if (ps >= 3) ps -= 3;
            prefetch(c + 2, ps);
            CP_COMMIT();
        }

        const uint32_t* A = (const uint32_t*)(smf + slot * SFL);
        const uint32_t* B = A + AFL;
        #pragma unroll
        for (int ks = 0; ks < 4; ks++) {
            uint32_t a[MF][4], b[NF][2];
            const int s0 = ((2 * ks) ^ g) * 4 + tq;
            const int s1 = s0 ^ 4;
            #pragma unroll
            for (int mf = 0; mf < MF; mf++) {
                const int ar = wm * (16 * MF) + mf * 16 + g;   // ar&7 == g
                a[mf][0] = A[ar * 32 + s0];
                a[mf][1] = A[(ar + 8) * 32 + s0];
                a[mf][2] = A[ar * 32 + s1];
                a[mf][3] = A[(ar + 8) * 32 + s1];
            }
            const int bkr = ks * 8 + tq;
            #pragma unroll
            for (int nf = 0; nf < NF; nf++) {
                const int bcc = wn * WNT + nf * 8 + g;
                b[nf][0] = B[bkr * BST + bcc];
                b[nf][1] = B[(bkr + 4) * BST + bcc];
            }
            #pragma unroll
            for (int mf = 0; mf < MF; mf++)
                #pragma unroll
                for (int nf = 0; nf < NF; nf++)
                    mma_tf32(d[mf][nf], a[mf], b[nf]);
        }
        if (++slot == 3) slot = 0;
    }

    if (OMODE == 1) {
        #pragma unroll
        for (int nf = 0; nf < NF; nf++) {
            const int col = ncta + wn * WNT + nf * 8 + 2 * tq;
            const float b0 = __ldg(bias + col);
            const float b1 = __ldg(bias + col + 1);
            #pragma unroll
            for (int mf = 0; mf < MF; mf++) {
                const int row0s = blockIdx.x * TM + wm * (16 * MF) + mf * 16 + g;
                float2 v0, v1;
                v0.x = f2tf32f(fmaxf(d[mf][nf][0] + b0, 0.f));
                v0.y = f2tf32f(fmaxf(d[mf][nf][1] + b1, 0.f));
                v1.x = f2tf32f(fmaxf(d[mf][nf][2] + b0, 0.f));
                v1.y = f2tf32f(fmaxf(d[mf][nf][3] + b1, 0.f));
                *(float2*)(out + (size_t)row0s * COUTG + col)       = v0;
                *(float2*)(out + (size_t)(row0s + 8) * COUTG + col) = v1;
            }
        }
    } else {
        // OMODE == 2: fused pooling. TM == P: this CTA = one image, NTILE channels.
        __syncthreads();
        float s[NF][2];
        #pragma unroll
        for (int nf = 0; nf < NF; nf++) {
            const int col = ncta + wn * WNT + nf * 8 + 2 * tq;
            const float b0 = __ldg(bias + col);
            const float b1 = __ldg(bias + col + 1);
            float s0 = 0.f, s1 = 0.f;
            #pragma unroll
            for (int mf = 0; mf < MF; mf++) {
                s0 += fmaxf(d[mf][nf][0] + b0, 0.f) + fmaxf(d[mf][nf][2] + b0, 0.f);
                s1 += fmaxf(d[mf][nf][1] + b1, 0.f) + fmaxf(d[mf][nf][3] + b1, 0.f);
            }
            #pragma unroll
            for (int o = 16; o >= 4; o >>= 1) {
                s0 += __shfl_xor_sync(0xffffffffu, s0, o);
                s1 += __shfl_xor_sync(0xffffffffu, s1, o);
            }
            s[nf][0] = s0; s[nf][1] = s1;
        }
        float* ps = smf;
        if (g == 0) {
            #pragma unroll
            for (int nf = 0; nf < NF; nf++) {
                ps[((wid * NF + nf) * 4 + tq) * 2 + 0] = s[nf][0];
                ps[((wid * NF + nf) * 4 + tq) * 2 + 1] = s[nf][1];
            }
        }
        __syncthreads();
        if (tid < NTILE) {
            const int wn_c = tid / WNT;
            const int rr   = tid % WNT;
            const int nf_c = rr >> 3;
            const int tq_c = (rr & 7) >> 1;
            const int j    = rr & 1;
            float sum = 0.f;
            #pragma unroll
            for (int wmc = 0; wmc < WM; wmc++) {
                const int w = wn_c * WM + wmc;
                sum += ps[((w * NF + nf_c) * 4 + tq_c) * 2 + j];
            }
            const int img = (blockIdx.x * TM) / P;
            out[(size_t)img * 256 + ncta + tid] = sum;
        }
    }
}

// ---------------- pool stage 2: sum over C=32 heads, divide ----------------
__global__ void pool2()
{
    const int b = blockIdx.x;
    const int k = threadIdx.x;
    const float* __restrict__ p = g_pp + (size_t)b * 32 * 256 + k;
    float s = 0.0f;
    #pragma unroll
    for (int c = 0; c < 32; c++)
        s += p[(size_t)c * 256];
    g_pbar[b * 256 + k] = s * (1.0f / 2048.0f);
}

// ---------------- FC ----------------
__global__ void fc_kernel(const float* __restrict__ Wfc, const float* __restrict__ bfc,
                          float* __restrict__ out)
{
    const int b = blockIdx.x;
    const int l = threadIdx.x;
    float s = bfc[l];
    const float* p = g_pbar + b * 256;
    #pragma unroll 8
    for (int k = 0; k < 256; k++)
        s = fmaf(p[k], Wfc[k * LATENT + l], s);
    out[b * LATENT + l] = s;
}

// ---------------- launch ----------------
extern "C" void kernel_launch(void* const* d_in, const int* in_sizes, int n_in,
                              void* d_out, int out_size)
{
    const float* x_raw = (const float*)d_in[0];
    const float* W1 = (const float*)d_in[1];  const float* b1 = (const float*)d_in[2];
    const float* W2 = (const float*)d_in[3];  const float* b2 = (const float*)d_in[4];
    const float* W3 = (const float*)d_in[5];  const float* b3 = (const float*)d_in[6];
    const float* W4 = (const float*)d_in[7];  const float* b4 = (const float*)d_in[8];
    const float* Wfc = (const float*)d_in[9]; const float* bfc = (const float*)d_in[10];
    float* out = (float*)d_out;

    float *gaf, *h1, *h2, *h3, *pp, *wr1, *wr2, *wr3, *wr4;
    cudaGetSymbolAddress((void**)&gaf, g_gaf);
    cudaGetSymbolAddress((void**)&h1, g_h1);
    cudaGetSymbolAddress((void**)&h2, g_h2);
    cudaGetSymbolAddress((void**)&h3, g_h3);
    cudaGetSymbolAddress((void**)&pp, g_pp);
    cudaGetSymbolAddress((void**)&wr1, g_wr1);
    cudaGetSymbolAddress((void**)&wr2, g_wr2);
    cudaGetSymbolAddress((void**)&wr3, g_wr3);
    cudaGetSymbolAddress((void**)&wr4, g_wr4);

    // conv1_mma: 1 stage (A 128x36 + B 32x40) = 23.5 KB
    const int smem1 = (128 * 36 + 32 * 40) * 4;
    // conv_mma L2-L4: 3 stages of (packed A + B); 76.8KB per CTA -> 2 CTAs/SM
    const int smem2 = 3 * (128 * 32 + 32 * 72)  * 4;   // 76800
    const int smem3 = 3 * (64  * 32 + 32 * 136) * 4;   // 76800
    const int smem4 = 3 * (64  * 32 + 32 * 136) * 4;   // 76800
    cudaFuncSetAttribute((const void*)conv1_mma,
                         cudaFuncAttributeMaxDynamicSharedMemorySize, smem1);
    cudaFuncSetAttribute((const void*)conv_mma<32, 64, 64, 64, 128, 2, 2, 1>,
                         cudaFuncAttributeMaxDynamicSharedMemorySize, smem2);
    cudaFuncSetAttribute((const void*)conv_mma<64, 32, 128, 128, 64, 2, 2, 1>,
                         cudaFuncAttributeMaxDynamicSharedMemorySize, smem3);
    cudaFuncSetAttribute((const void*)conv_mma<128, 16, 256, 128, 64, 2, 2, 2>,
                         cudaFuncAttributeMaxDynamicSharedMemorySize, smem4);

    const int rp_total = 1024 + 288 * 64 + 576 * 128 + 1152 * 256;

    repack_all<<<(rp_total + 255) / 256, 256>>>(W1, W2, W3, W4);       // 0
    gaf_kernel<<<NIMG, 128>>>(x_raw);                                  // 1
    // L1: tf32 MMA, single chunk, M=128 N=32
    conv1_mma<<<NIMG * 4096 / 128, 128, smem1>>>(gaf, wr1, b1, h1);    // 2
    // L2: TM=128, warp tile 64x32 (MF=4, NF=4), 9 chunks
    conv_mma<32, 64, 64, 64, 128, 2, 2, 1>
        <<<dim3(NIMG * 1024 / 128, 1), 128, smem2>>>(h1, wr2, b2, h2); // 3
    // L3: TM=64, warp tile 32x64 (MF=2, NF=8), 18 chunks
    conv_mma<64, 32, 128, 128, 64, 2, 2, 1>
        <<<dim3(NIMG * 256 / 64, 1), 128, smem3>>>(h2, wr3, b3, h3);   // 4
    // L4: TM=64 (= one image), N split 2x128, fused pooling -> g_pp
    conv_mma<128, 16, 256, 128, 64, 2, 2, 2>
        <<<dim3(NIMG, 2), 128, smem4>>>(h3, wr4, b4, pp);              // 5
    pool2<<<BB, 256>>>();                                              // 6
    fc_kernel<<<BB, LATENT>>>(Wfc, bfc, out);                          // 7
}

// round 17
// speedup vs baseline: 3.0611x; 1.2735x over previous
#include <cuda_runtime.h>
#include <cuda_fp16.h>
#include <cstdint>
#include <math.h>

// Problem constants
#define BB 16
#define CC 32
#define TT 512
#define SS 128       // GAF_SIZE
#define NIMG (BB*CC) // 512
#define LATENT 128

// ---------------- scratch (no allocation allowed) ----------------
__device__ __half g_gaf[(size_t)NIMG * SS * SS * 2];     // NHWC (C=2) fp16
__device__ __half g_h1 [(size_t)NIMG * 64 * 64 * 32];    // NHWC fp16
__device__ __half g_h2 [(size_t)NIMG * 32 * 32 * 64];    // NHWC fp16
__device__ __half g_h3 [(size_t)NIMG * 16 * 16 * 128];   // NHWC fp16
__device__ float  g_pp  [NIMG * 256];                    // per-image pooled sums (fp32)
__device__ float  g_pbar[BB * 256];
__device__ __half g_wr1[32 * 32];                        // L1: [n][k], k=kh*8+kw*2+ci (pad 0)
__device__ __half g_wr2[9  * 64  * 32];                  // [kc][n][32] fp16
__device__ __half g_wr3[18 * 128 * 32];
__device__ __half g_wr4[36 * 256 * 32];

// ---------------- helpers ----------------
__device__ __forceinline__ void mma_f16(float* d, const uint32_t* a, const uint32_t* b) {
    asm volatile(
        "mma.sync.aligned.m16n8k16.row.col.f32.f16.f16.f32 "
        "{%0,%1,%2,%3}, {%4,%5,%6,%7}, {%8,%9}, {%0,%1,%2,%3};"
        : "+f"(d[0]), "+f"(d[1]), "+f"(d[2]), "+f"(d[3])
        : "r"(a[0]), "r"(a[1]), "r"(a[2]), "r"(a[3]), "r"(b[0]), "r"(b[1]));
}
__device__ __forceinline__ uint32_t smem_u32(const void* p) {
    uint32_t a;
    asm("{ .reg .u64 t; cvta.to.shared.u64 t, %1; cvt.u32.u64 %0, t; }" : "=r"(a) : "l"(p));
    return a;
}
__device__ __forceinline__ void cpasync16(uint32_t dst, const void* src, int srcsize) {
    asm volatile("cp.async.cg.shared.global [%0], [%1], 16, %2;"
                 :: "r"(dst), "l"(src), "r"(srcsize) : "memory");
}
__device__ __forceinline__ void cpasync8(uint32_t dst, const void* src, int srcsize) {
    asm volatile("cp.async.ca.shared.global [%0], [%1], 8, %2;"
                 :: "r"(dst), "l"(src), "r"(srcsize) : "memory");
}
__device__ __forceinline__ void cpasync4(uint32_t dst, const void* src, int srcsize) {
    asm volatile("cp.async.ca.shared.global [%0], [%1], 4, %2;"
                 :: "r"(dst), "l"(src), "r"(srcsize) : "memory");
}
#define CP_COMMIT() asm volatile("cp.async.commit_group;" ::: "memory")
#define CP_WAIT1()  asm volatile("cp.async.wait_group 1;" ::: "memory")
#define CP_WAIT0()  asm volatile("cp.async.wait_group 0;" ::: "memory")

// ---------------- merged weight repack (fp16, B n-major per chunk) ----------------
__device__ __forceinline__ void rp_tc(const float* __restrict__ W, __half* __restrict__ Br,
                                      int CIN, int COUT, int idx)
{
    // Br[kc][n][kk]
    int kk = idx & 31;
    int n  = (idx >> 5) % COUT;
    int kc = idx / (COUT * 32);
    int k  = kc * 32 + kk;
    int t  = k / CIN;
    int ci = k % CIN;
    Br[idx] = __float2half_rn(W[((size_t)n * CIN + ci) * 9 + t]);
}
__global__ void repack_all(const float* __restrict__ W1, const float* __restrict__ W2,
                           const float* __restrict__ W3, const float* __restrict__ W4)
{
    int idx = blockIdx.x * blockDim.x + threadIdx.x;
    if (idx < 1024) {                      // L1: [n][k], k = kh*8 + kw*2 + ci
        int n = idx >> 5;
        int k = idx & 31;
        int kh = k >> 3, r = k & 7;
        float v = 0.0f;
        if (kh < 3 && r < 6) {
            int kw = r >> 1, ci = r & 1;
            v = W1[((size_t)(n * 2 + ci)) * 9 + kh * 3 + kw];
        }
        g_wr1[idx] = __float2half_rn(v);
        return;
    }
    idx -= 1024;
    if (idx < 9 * 64 * 32)   { rp_tc(W2, g_wr2, 32, 64, idx);   return; }
    idx -= 9 * 64 * 32;
    if (idx < 18 * 128 * 32) { rp_tc(W3, g_wr3, 64, 128, idx);  return; }
    idx -= 18 * 128 * 32;
    if (idx < 36 * 256 * 32) rp_tc(W4, g_wr4, 128, 256, idx);
}

// ---------------- GAF kernel: NHWC (C=2) fp16 output ----------------
__global__ void gaf_kernel(const float* __restrict__ x_raw)
{
    const int img = blockIdx.x;
    const int tid = threadIdx.x;   // 0..127
    __shared__ float xs[SS];
    __shared__ float ssq[SS];
    __shared__ float smn[4], smx[4];

    const float4 v4 = *(const float4*)(x_raw + (size_t)img * TT + tid * 4);
    float v = 0.25f * (v4.x + v4.y + v4.z + v4.w);

    float mn = v, mx = v;
    #pragma unroll
    for (int o = 16; o > 0; o >>= 1) {
        mn = fminf(mn, __shfl_xor_sync(0xffffffffu, mn, o));
        mx = fmaxf(mx, __shfl_xor_sync(0xffffffffu, mx, o));
    }
    const int warp = tid >> 5, lane = tid & 31;
    if (lane == 0) { smn[warp] = mn; smx[warp] = mx; }
    __syncthreads();
    mn = fminf(fminf(smn[0], smn[1]), fminf(smn[2], smn[3]));
    mx = fmaxf(fmaxf(smx[0], smx[1]), fmaxf(smx[2], smx[3]));

    float xn = 2.0f * (v - mn) / (mx - mn + 1e-8f) - 1.0f;
    xn = fminf(1.0f, fmaxf(-1.0f, xn));
    float sq = sqrtf(fminf(1.0f, fmaxf(0.0f, 1.0f - xn * xn)));
    xs[tid] = xn;
    ssq[tid] = sq;
    __syncthreads();

    const int c0 = lane * 4;
    float xj[4], sj[4];
    #pragma unroll
    for (int c = 0; c < 4; c++) { xj[c] = xs[c0 + c]; sj[c] = ssq[c0 + c]; }
    __half* __restrict__ gb = g_gaf + (size_t)img * (SS * SS * 2);
    for (int rb = 0; rb < SS; rb += 4) {
        const int row = rb + warp;
        const float xi = xs[row], si = ssq[row];
        __half2 h[4];
        #pragma unroll
        for (int c = 0; c < 4; c++)
            h[c] = __floats2half2_rn(xi * xj[c] - si * sj[c],   // ch0 = gasf
                                     si * xj[c] - xi * sj[c]);  // ch1 = gadf
        uint4 u;
        u.x = *(uint32_t*)&h[0]; u.y = *(uint32_t*)&h[1];
        u.z = *(uint32_t*)&h[2]; u.w = *(uint32_t*)&h[3];
        *(uint4*)(gb + ((size_t)row * SS + c0) * 2) = u;
    }
}

// ---------------- L1 conv via fp16 MMA (single chunk K=32 incl pads) ----------------
// in: g_gaf NHWC C=2 fp16; Br: g_wr1 [n][32]; out: h1 NHWC 32ch fp16.
// M tile 128, N=32, warps 2x2 (warp tile 64x16: MF=4, NF=2), 2 ks-steps.
__global__ void __launch_bounds__(128)
conv1_mma(const __half* __restrict__ in, const __half* __restrict__ Br,
          const float* __restrict__ bias, __half* __restrict__ out)
{
    constexpr int AST = 40;                 // halves per A row (80B, odd-stride bank trick)
    constexpr int BST = 40;
    constexpr int AFL = 128 * AST;
    constexpr int HIN = 128, P = 4096;

    extern __shared__ __half smh[];
    const uint32_t sm0 = smem_u32(smh);

    const int tid  = threadIdx.x;
    const int lane = tid & 31;
    const int wid  = tid >> 5;
    const int wm   = wid & 1;
    const int wn   = wid >> 1;
    const int g    = lane >> 2;
    const int tq   = lane & 3;

    // A staging: thread = row
    const int pos = blockIdx.x * 128 + tid;
    const int n   = pos >> 12;
    const int rem = pos & (P - 1);
    const int oh  = rem >> 6, ow = rem & 63;
    const __half* base = in + (((size_t)n * HIN + 2 * oh) * HIN + 2 * ow) * 2;
    const uint32_t ad = sm0 + (uint32_t)tid * AST * 2;

    // zero pad columns: {6,7},{14,15},{22,23} and 24..31
    {
        __half* Arow = smh + tid * AST;
        *(uint32_t*)(Arow + 6)  = 0u;
        *(uint32_t*)(Arow + 14) = 0u;
        *(uint32_t*)(Arow + 22) = 0u;
        *(uint4*)(Arow + 24) = make_uint4(0u, 0u, 0u, 0u);
    }

    #pragma unroll
    for (int kh = 0; kh < 3; kh++) {
        const bool v8 = !(oh == 63 && kh == 2);
        const bool v4 = v8 && (ow != 63);
        const __half* s = base + kh * (HIN * 2);
        cpasync8(ad + kh * 16,     s,     v8 ? 8 : 0);   // kw=0,1 (4 halves)
        cpasync4(ad + kh * 16 + 8, s + 4, v4 ? 4 : 0);   // kw=2   (2 halves)
    }
    // B: 32 rows x 32 halves (64B each): thread -> (n=tid>>2, k16=tid&3)
    {
        const uint32_t bd = sm0 + (uint32_t)AFL * 2;
        const int k16 = tid & 3, bn = tid >> 2;
        cpasync16(bd + (uint32_t)(bn * BST * 2 + k16 * 16), Br + bn * 32 + k16 * 8, 16);
    }
    CP_COMMIT();

    float d[4][2][4];
    #pragma unroll
    for (int mf = 0; mf < 4; mf++)
        #pragma unroll
        for (int nf = 0; nf < 2; nf++)
            #pragma unroll
            for (int j = 0; j < 4; j++) d[mf][nf][j] = 0.f;

    CP_WAIT0();
    __syncthreads();

    const __half* A  = smh;
    const __half* Bt = smh + AFL;
    #pragma unroll
    for (int ks = 0; ks < 2; ks++) {
        uint32_t a[4][4], b[2][2];
        const int colL = ks * 16 + 2 * tq;
        #pragma unroll
        for (int mf = 0; mf < 4; mf++) {
            const int ar = wm * 64 + mf * 16 + g;
            a[mf][0] = *(const uint32_t*)(A + ar * AST + colL);
            a[mf][1] = *(const uint32_t*)(A + (ar + 8) * AST + colL);
            a[mf][2] = *(const uint32_t*)(A + ar * AST + colL + 8);
            a[mf][3] = *(const uint32_t*)(A + (ar + 8) * AST + colL + 8);
        }
        #pragma unroll
        for (int nf = 0; nf < 2; nf++) {
            const int bn = wn * 16 + nf * 8 + g;
            b[nf][0] = *(const uint32_t*)(Bt + bn * BST + colL);
            b[nf][1] = *(const uint32_t*)(Bt + bn * BST + colL + 8);
        }
        #pragma unroll
        for (int mf = 0; mf < 4; mf++)
            #pragma unroll
            for (int nf = 0; nf < 2; nf++)
                mma_f16(d[mf][nf], a[mf], b[nf]);
    }

    // epilogue: bias + ReLU, half2 stores
    #pragma unroll
    for (int nf = 0; nf < 2; nf++) {
        const int col = wn * 16 + nf * 8 + 2 * tq;
        const float b0 = __ldg(bias + col);
        const float b1 = __ldg(bias + col + 1);
        #pragma unroll
        for (int mf = 0; mf < 4; mf++) {
            const int row0s = blockIdx.x * 128 + wm * 64 + mf * 16 + g;
            __half2 v0 = __floats2half2_rn(fmaxf(d[mf][nf][0] + b0, 0.f),
                                           fmaxf(d[mf][nf][1] + b1, 0.f));
            __half2 v1 = __floats2half2_rn(fmaxf(d[mf][nf][2] + b0, 0.f),
                                           fmaxf(d[mf][nf][3] + b1, 0.f));
            *(__half2*)(out + (size_t)row0s * 32 + col)       = v0;
            *(__half2*)(out + (size_t)(row0s + 8) * 32 + col) = v1;
        }
    }
}

// ---------------- fp16 mma implicit-GEMM conv (layers 2-4) ----------------
// r15 skeleton: 3-stage ring, 1 chunk/barrier, CP_WAIT1, 4 warps, 128 thr.
// A/B smem rows = 40 halves (80B odd stride: conflict-free stage + frag loads).
// OMODE: 1 = fp16 NHWC store; 2 = fused global pooling -> g_pp (TM == P).
template<int CIN, int HIN, int COUTG, int NTILE, int TM, int WM, int WN, int OMODE>
__global__ void __launch_bounds__(128)
conv_mma(const __half* __restrict__ in, const __half* __restrict__ Br,
         const float* __restrict__ bias, void* __restrict__ outv)
{
    static_assert(WM * WN == 4, "4 warps");
    constexpr int HOUT = HIN / 2;
    constexpr int P    = HOUT * HOUT;
    constexpr int K    = CIN * 9;
    constexpr int NCH  = K / 32;
    constexpr int CPT  = CIN / 32;
    constexpr int MF   = TM / (WM * 16);
    constexpr int WNT  = NTILE / WN;
    constexpr int NF   = WNT / 8;
    constexpr int AST  = 40;               // halves
    constexpr int BST  = 40;
    constexpr int AFL  = TM * AST;
    constexpr int BFL  = NTILE * BST;
    constexpr int SFL  = AFL + BFL;        // halves per stage
    constexpr int AIT  = TM / 32;          // A cp.async per thread (4 chunks/row)
    constexpr int BCH  = NTILE / 32;       // B cp.async per thread

    extern __shared__ __half smh[];
    const uint32_t sm0 = smem_u32(smh);

    const int tid  = threadIdx.x;
    const int lane = tid & 31;
    const int wid  = tid >> 5;
    const int wm   = wid % WM;
    const int wn   = wid / WM;
    const int g    = lane >> 2;
    const int tq   = lane & 3;

    const int ncta = blockIdx.y * NTILE;

    // A staging: c16 = tid&3 (16B chunk of 64B row), row0 = tid>>2
    const int c16  = tid & 3;
    const int row0 = tid >> 2;
    int abase[AIT];
    uint32_t bflags = 0;
    #pragma unroll
    for (int it = 0; it < AIT; it++) {
        const int row = row0 + 32 * it;
        const int pos = blockIdx.x * TM + row;
        const int n   = pos / P;
        const int rem = pos % P;
        const int oh  = rem / HOUT, ow = rem % HOUT;
        abase[it] = ((n * HIN + 2 * oh) * HIN + 2 * ow) * CIN + c16 * 8;
        if (oh == HOUT - 1) bflags |= 1u << (2 * it);
        if (ow == HOUT - 1) bflags |= 2u << (2 * it);
    }

    auto prefetch = [&](int kc, int slot) {
        const uint32_t sbase = sm0 + (uint32_t)(slot * SFL) * 2;
        const int t   = kc / CPT;
        const int ci0 = (kc % CPT) * 32;
        const int kh = t / 3, kw = t % 3;
        const int tap = (kh * HIN + kw) * CIN + ci0;
        #pragma unroll
        for (int it = 0; it < AIT; it++) {
            const bool val = !(((bflags >> (2 * it)) & 1u) && kh == 2) &&
                             !(((bflags >> (2 * it)) & 2u) && kw == 2);
            const __half* s = val ? (in + abase[it] + tap) : in;
            cpasync16(sbase + (uint32_t)((row0 + 32 * it) * AST * 2 + c16 * 16),
                      s, val ? 16 : 0);
        }
        // B: NTILE rows x 32 halves, n-major source [kc][COUTG][32]
        const uint32_t bd = sbase + (uint32_t)AFL * 2;
        #pragma unroll
        for (int j = 0; j < BCH; j++) {
            const int cid = j * 128 + tid;
            const int k16 = cid & 3;
            const int bn  = cid >> 2;
            cpasync16(bd + (uint32_t)(bn * BST * 2 + k16 * 16),
                      Br + ((size_t)kc * COUTG + ncta + bn) * 32 + k16 * 8, 16);
        }
    };

    prefetch(0, 0); CP_COMMIT();
    prefetch(1, 1); CP_COMMIT();

    float d[MF][NF][4];
    #pragma unroll
    for (int mf = 0; mf < MF; mf++)
        #pragma unroll
        for (int nf = 0; nf < NF; nf++)
            #pragma unroll
            for (int j = 0; j < 4; j++) d[mf][nf][j] = 0.f;

    int slot = 0;
    for (int c = 0; c < NCH; c++) {
        if (c + 1 < NCH) { CP_WAIT1(); } else { CP_WAIT0(); }
        __syncthreads();
        if (c + 2 < NCH) {
            int ps = slot + 2; if (ps >= 3) ps -= 3;
            prefetch(c + 2, ps);
            CP_COMMIT();
        }

        const __half* A  = smh + slot * SFL;
        const __half* Bt = A + AFL;
        #pragma unroll
        for (int ks = 0; ks < 2; ks++) {
            uint32_t a[MF][4], b[NF][2];
            const int colL = ks * 16 + 2 * tq;
            #pragma unroll
            for (int mf = 0; mf < MF; mf++) {
                const int ar = wm * (16 * MF) + mf * 16 + g;
                a[mf][0] = *(const uint32_t*)(A + ar * AST + colL);
                a[mf][1] = *(const uint32_t*)(A + (ar + 8) * AST + colL);
                a[mf][2] = *(const uint32_t*)(A + ar * AST + colL + 8);
                a[mf][3] = *(const uint32_t*)(A + (ar + 8) * AST + colL + 8);
            }
            #pragma unroll
            for (int nf = 0; nf < NF; nf++) {
                const int bn = wn * WNT + nf * 8 + g;
                b[nf][0] = *(const uint32_t*)(Bt + bn * BST + colL);
                b[nf][1] = *(const uint32_t*)(Bt + bn * BST + colL + 8);
            }
            #pragma unroll
            for (int mf = 0; mf < MF; mf++)
                #pragma unroll
                for (int nf = 0; nf < NF; nf++)
                    mma_f16(d[mf][nf], a[mf], b[nf]);
        }
        if (++slot == 3) slot = 0;
    }

    if (OMODE == 1) {
        __half* out = (__half*)outv;
        #pragma unroll
        for (int nf = 0; nf < NF; nf++) {
            const int col = ncta + wn * WNT + nf * 8 + 2 * tq;
            const float b0 = __ldg(bias + col);
            const float b1 = __ldg(bias + col + 1);
            #pragma unroll
            for (int mf = 0; mf < MF; mf++) {
                const int row0s = blockIdx.x * TM + wm * (16 * MF) + mf * 16 + g;
                __half2 v0 = __floats2half2_rn(fmaxf(d[mf][nf][0] + b0, 0.f),
                                               fmaxf(d[mf][nf][1] + b1, 0.f));
                __half2 v1 = __floats2half2_rn(fmaxf(d[mf][nf][2] + b0, 0.f),
                                               fmaxf(d[mf][nf][3] + b1, 0.f));
                *(__half2*)(out + (size_t)row0s * COUTG + col)       = v0;
                *(__half2*)(out + (size_t)(row0s + 8) * COUTG + col) = v1;
            }
        }
    } else {
        // OMODE == 2: fused pooling (TM == P, one image per CTA). fp32 sums.
        float* out = (float*)outv;
        __syncthreads();
        float s[NF][2];
        #pragma unroll
        for (int nf = 0; nf < NF; nf++) {
            const int col = ncta + wn * WNT + nf * 8 + 2 * tq;
            const float b0 = __ldg(bias + col);
            const float b1 = __ldg(bias + col + 1);
            float s0 = 0.f, s1 = 0.f;
            #pragma unroll
            for (int mf = 0; mf < MF; mf++) {
                s0 += fmaxf(d[mf][nf][0] + b0, 0.f) + fmaxf(d[mf][nf][2] + b0, 0.f);
                s1 += fmaxf(d[mf][nf][1] + b1, 0.f) + fmaxf(d[mf][nf][3] + b1, 0.f);
            }
            #pragma unroll
            for (int o = 16; o >= 4; o >>= 1) {
                s0 += __shfl_xor_sync(0xffffffffu, s0, o);
                s1 += __shfl_xor_sync(0xffffffffu, s1, o);
            }
            s[nf][0] = s0; s[nf][1] = s1;
        }
        float* ps = (float*)smh;
        if (g == 0) {
            #pragma unroll
            for (int nf = 0; nf < NF; nf++) {
                ps[((wid * NF + nf) * 4 + tq) * 2 + 0] = s[nf][0];
                ps[((wid * NF + nf) * 4 + tq) * 2 + 1] = s[nf][1];
            }
        }
        __syncthreads();
        if (tid < NTILE) {
            const int wn_c = tid / WNT;
            const int rr   = tid % WNT;
            const int nf_c = rr >> 3;
            const int tq_c = (rr & 7) >> 1;
            const int j    = rr & 1;
            float sum = 0.f;
            #pragma unroll
            for (int wmc = 0; wmc < WM; wmc++) {
                const int w = wn_c * WM + wmc;
                sum += ps[((w * NF + nf_c) * 4 + tq_c) * 2 + j];
            }
            const int img = (blockIdx.x * TM) / P;
            out[(size_t)img * 256 + ncta + tid] = sum;
        }
    }
}

// ---------------- pool stage 2: sum over C=32 heads, divide ----------------
__global__ void pool2()
{
    const int b = blockIdx.x;
    const int k = threadIdx.x;
    const float* __restrict__ p = g_pp + (size_t)b * 32 * 256 + k;
    float s = 0.0f;
    #pragma unroll
    for (int c = 0; c < 32; c++)
        s += p[(size_t)c * 256];
    g_pbar[b * 256 + k] = s * (1.0f / 2048.0f);
}

// ---------------- FC ----------------
__global__ void fc_kernel(const float* __restrict__ Wfc, const float* __restrict__ bfc,
                          float* __restrict__ out)
{
    const int b = blockIdx.x;
    const int l = threadIdx.x;
    float s = bfc[l];
    const float* p = g_pbar + b * 256;
    #pragma unroll 8
    for (int k = 0; k < 256; k++)
        s = fmaf(p[k], Wfc[k * LATENT + l], s);
    out[b * LATENT + l] = s;
}

// ---------------- launch ----------------
extern "C" void kernel_launch(void* const* d_in, const int* in_sizes, int n_in,
                              void* d_out, int out_size)
{
    const float* x_raw = (const float*)d_in[0];
    const float* W1 = (const float*)d_in[1];  const float* b1 = (const float*)d_in[2];
    const float* W2 = (const float*)d_in[3];  const float* b2 = (const float*)d_in[4];
    const float* W3 = (const float*)d_in[5];  const float* b3 = (const float*)d_in[6];
    const float* W4 = (const float*)d_in[7];  const float* b4 = (const float*)d_in[8];
    const float* Wfc = (const float*)d_in[9]; const float* bfc = (const float*)d_in[10];
    float* out = (float*)d_out;

    __half *gaf, *h1, *h2, *h3, *wr1, *wr2, *wr3, *wr4;
    float *pp;
    cudaGetSymbolAddress((void**)&gaf, g_gaf);
    cudaGetSymbolAddress((void**)&h1, g_h1);
    cudaGetSymbolAddress((void**)&h2, g_h2);
    cudaGetSymbolAddress((void**)&h3, g_h3);
    cudaGetSymbolAddress((void**)&pp, g_pp);
    cudaGetSymbolAddress((void**)&wr1, g_wr1);
    cudaGetSymbolAddress((void**)&wr2, g_wr2);
    cudaGetSymbolAddress((void**)&wr3, g_wr3);
    cudaGetSymbolAddress((void**)&wr4, g_wr4);

    // smem: halves * 2 bytes
    const int smem1 = (128 * 40 + 32 * 40) * 2;            // 12800
    const int smem2 = 3 * (128 * 40 + 64 * 40) * 2;        // 46080
    const int smem3 = 3 * (64 * 40 + 128 * 40) * 2;        // 46080
    const int smem4 = smem3;
    cudaFuncSetAttribute((const void*)conv1_mma,
                         cudaFuncAttributeMaxDynamicSharedMemorySize, smem1);
    cudaFuncSetAttribute((const void*)conv_mma<32, 64, 64, 64, 128, 2, 2, 1>,
                         cudaFuncAttributeMaxDynamicSharedMemorySize, smem2);
    cudaFuncSetAttribute((const void*)conv_mma<64, 32, 128, 128, 64, 2, 2, 1>,
                         cudaFuncAttributeMaxDynamicSharedMemorySize, smem3);
    cudaFuncSetAttribute((const void*)conv_mma<128, 16, 256, 128, 64, 2, 2, 2>,
                         cudaFuncAttributeMaxDynamicSharedMemorySize, smem4);

    const int rp_total = 1024 + 9 * 64 * 32 + 18 * 128 * 32 + 36 * 256 * 32;

    repack_all<<<(rp_total + 255) / 256, 256>>>(W1, W2, W3, W4);       // 0
    gaf_kernel<<<NIMG, 128>>>(x_raw);                                  // 1
    conv1_mma<<<NIMG * 4096 / 128, 128, smem1>>>(gaf, wr1, b1, h1);    // 2
    // L2: TM=128, warp tile 64x32 (MF=4, NF=4), 9 chunks
    conv_mma<32, 64, 64, 64, 128, 2, 2, 1>
        <<<dim3(NIMG * 1024 / 128, 1), 128, smem2>>>(h1, wr2, b2, h2); // 3
    // L3: TM=64, warp tile 32x64 (MF=2, NF=8), 18 chunks
    conv_mma<64, 32, 128, 128, 64, 2, 2, 1>
        <<<dim3(NIMG * 256 / 64, 1), 128, smem3>>>(h2, wr3, b3, h3);   // 4
    // L4: TM=64 (= one image), N split 2x128, fused pooling -> g_pp
    conv_mma<128, 16, 256, 128, 64, 2, 2, 2>
        <<<dim3(NIMG, 2), 128, smem4>>>(h3, wr4, b4, pp);              // 5
    pool2<<<BB, 256>>>();                                              // 6
    fc_kernel<<<BB, LATENT>>>(Wfc, bfc, out);                          // 7
}